// round 8
// baseline (speedup 1.0000x reference)
#include <cuda_runtime.h>
#include <cuda_fp16.h>
#include <math.h>
#include <stdint.h>

// ---------------- problem constants ----------------
#define BB      2
#define CC      1024
#define TT      1024
#define TOKS    (BB * TT)          // 2048
#define DIN     2048
#define DSTATE  16
#define DTRANK  64
#define XDBL    96
#define DCONV   4
#define SPLITK  16
#define SW      64                 // scan window (t-steps)

// ---------------- fp32 scratch ----------------
__device__ float g_xz  [TOKS * 2 * DIN];
__device__ float g_xc  [TOKS * DIN];
__device__ float g_xdbl[TOKS * XDBL];
__device__ float g_dt  [TOKS * DIN];
__device__ float g_part[SPLITK * TOKS * XDBL];

// ---------------- fp16 2-term split scratch (acts:[hi,lo], weights:[hi,hi]) ----------------
__device__ __half e_xn [TOKS * 2 * CC];
__device__ __half e_w1 [2 * DIN * 2 * CC];
__device__ __half e_xc [TOKS * 2 * DIN];
__device__ __half e_w2 [XDBL * 2 * DIN];
__device__ __half e_dtr[TOKS * 2 * DTRANK];
__device__ __half e_w3 [DIN * 2 * DTRANK];
__device__ __half e_y  [TOKS * 2 * DIN];
__device__ __half e_w4 [CC * 2 * DIN];

__device__ __forceinline__ void split2h(float v, __half& hi, __half& lo) {
    hi = __float2half_rn(v);
    lo = __float2half_rn(v - __half2float(hi));
}

// ==================== PTX helpers ====================
__device__ __forceinline__ uint32_t smem_u32(const void* p) {
    uint32_t a;
    asm("{ .reg .u64 t; cvta.to.shared.u64 t, %1; cvt.u32.u64 %0, t; }" : "=r"(a) : "l"(p));
    return a;
}
__device__ __forceinline__ void cp16(uint32_t dst, const void* src, bool pred) {
    int sz = pred ? 16 : 0;
    asm volatile("cp.async.cg.shared.global [%0], [%1], 16, %2;\n" :: "r"(dst), "l"(src), "r"(sz));
}
__device__ __forceinline__ void ldsm4(uint32_t& r0, uint32_t& r1, uint32_t& r2, uint32_t& r3,
                                      uint32_t addr) {
    asm volatile("ldmatrix.sync.aligned.m8n8.x4.shared.b16 {%0,%1,%2,%3}, [%4];"
                 : "=r"(r0), "=r"(r1), "=r"(r2), "=r"(r3) : "r"(addr));
}
__device__ __forceinline__ void mma16816(float* c, const uint32_t* a, const uint32_t* b) {
    asm volatile("mma.sync.aligned.m16n8k16.row.col.f32.f16.f16.f32 "
                 "{%0,%1,%2,%3}, {%4,%5,%6,%7}, {%8,%9}, {%0,%1,%2,%3};"
                 : "+f"(c[0]), "+f"(c[1]), "+f"(c[2]), "+f"(c[3])
                 : "r"(a[0]), "r"(a[1]), "r"(a[2]), "r"(a[3]), "r"(b[0]), "r"(b[1]));
}

// ==================== mma.sync fp16 GEMM ====================
// C[M,N] = A[M,Kext] @ W[N,Kext]^T. Tile MT x NT, K-tile 64, 3-stage cp.async ring.
// 8 warps: 4 along M (MT/4 rows each), 2 along N (NT/2 cols each).
// OP 0 plain | OP 1 softplus+bias | OP 2 transpose+residual | OP 3 split-K partials
template <int OP, int MT, int NT>
__global__ __launch_bounds__(256, 1)
void gemm_mma(const __half* __restrict__ A, int lda,
              const __half* __restrict__ W, int ldw,
              float* __restrict__ C, int ldc,
              int M, int N, int Kext,
              const float* __restrict__ bias,
              const float* __restrict__ resid) {
    constexpr int SA     = MT * 128;
    constexpr int SB     = NT * 128;
    constexpr int STAGE  = SA + SB;
    constexpr int MTI    = MT / 64;         // m16 tiles per warp (2 or 4)
    constexpr int WROWS  = MT / 4;          // rows per warp
    constexpr int WCOLS  = NT / 2;          // cols per warp
    constexpr int NFR    = WCOLS / 8;
    constexpr int BLD    = WCOLS / 16;
    constexpr int ACHUNK = MT * 8 / 256;
    constexpr int BCHUNK = NT * 8 / 256;

    extern __shared__ float4 dyn4[];
    uint32_t base = smem_u32(dyn4);

    int tid = threadIdx.x, lane = tid & 31, warp = tid >> 5;
    int wm = warp & 3, wn = warp >> 2;
    int rowBase = blockIdx.y * MT, colBase = blockIdx.x * NT;

    int kStart = 0;
    if (OP == 3) {
        int ch = Kext / SPLITK;
        kStart = blockIdx.z * ch;
        Kext = ch;
        C += (size_t)blockIdx.z * M * ldc;
    }
    int nTiles = Kext / 64;

    float acc[MTI][NFR][4];
#pragma unroll
    for (int i = 0; i < MTI; i++)
#pragma unroll
        for (int j = 0; j < NFR; j++)
#pragma unroll
            for (int e = 0; e < 4; e++) acc[i][j][e] = 0.f;

    auto load_tile = [&](int s, int kt) {
        uint32_t aB = base + s * STAGE, bB = aB + SA;
        int k0 = kStart + kt * 64;
#pragma unroll
        for (int i = 0; i < ACHUNK; i++) {
            int idx = tid + i * 256;
            int row = idx >> 3, c = idx & 7;
            cp16(aB + row * 128 + ((c ^ (row & 7)) << 4),
                 A + (size_t)(rowBase + row) * lda + k0 + c * 8, true);
        }
#pragma unroll
        for (int i = 0; i < BCHUNK; i++) {
            int idx = tid + i * 256;
            int row = idx >> 3, c = idx & 7;
            bool ok = (colBase + row) < N;
            cp16(bB + row * 128 + ((c ^ (row & 7)) << 4),
                 W + (ok ? (size_t)(colBase + row) * ldw : 0) + k0 + c * 8, ok);
        }
        asm volatile("cp.async.commit_group;\n");
    };

    load_tile(0, 0);
    if (nTiles > 1) load_tile(1, 1);

    for (int t = 0; t < nTiles; t++) {
        if (t + 1 >= nTiles) asm volatile("cp.async.wait_group 0;\n");
        else                 asm volatile("cp.async.wait_group 1;\n");
        __syncthreads();

        int s = t % 3;
        uint32_t aB = base + s * STAGE, bB = aB + SA;
#pragma unroll
        for (int ks = 0; ks < 4; ks++) {
            uint32_t afr[MTI][4];
#pragma unroll
            for (int mt = 0; mt < MTI; mt++) {
                int row = wm * WROWS + mt * 16 + (lane & 15);
                int unit = ks * 2 + (lane >> 4);
                ldsm4(afr[mt][0], afr[mt][1], afr[mt][2], afr[mt][3],
                      aB + row * 128 + ((unit ^ (row & 7)) << 4));
            }
            uint32_t bfr[NFR][2];
#pragma unroll
            for (int p = 0; p < BLD; p++) {
                int row = wn * WCOLS + p * 16 + (lane & 15);
                int unit = ks * 2 + (lane >> 4);
                uint32_t r0, r1, r2, r3;
                ldsm4(r0, r1, r2, r3, bB + row * 128 + ((unit ^ (row & 7)) << 4));
                bfr[2 * p][0] = r0; bfr[2 * p + 1][0] = r1;
                bfr[2 * p][1] = r2; bfr[2 * p + 1][1] = r3;
            }
#pragma unroll
            for (int mt = 0; mt < MTI; mt++)
#pragma unroll
                for (int nt = 0; nt < NFR; nt++)
                    mma16816(acc[mt][nt], afr[mt], bfr[nt]);
        }
        if (t + 2 < nTiles) load_tile((t + 2) % 3, t + 2);
    }

    // ---- epilogue ----
#pragma unroll
    for (int mt = 0; mt < MTI; mt++) {
        int m = rowBase + wm * WROWS + mt * 16 + (lane >> 2);
#pragma unroll
        for (int nt = 0; nt < NFR; nt++) {
            int c0 = colBase + wn * WCOLS + nt * 8 + (lane & 3) * 2;
#pragma unroll
            for (int e = 0; e < 4; e++) {
                int mm = m + ((e >= 2) ? 8 : 0);
                int n = c0 + (e & 1);
                if (OP != 2 && n >= N) continue;
                float v = acc[mt][nt][e];
                if (OP == 0 || OP == 3) {
                    C[(size_t)mm * ldc + n] = v;
                } else if (OP == 1) {
                    v += bias[n];
                    C[(size_t)mm * ldc + n] = (v > 20.f) ? v : log1pf(__expf(v));
                } else {
                    int b = mm >> 10, tt2 = mm & 1023;
                    size_t oi = (size_t)b * CC * TT + (size_t)n * TT + tt2;
                    C[oi] = v + resid[oi];
                }
            }
        }
    }
}

// ==================== elementwise kernels ====================
__global__ __launch_bounds__(256) void ln_kernel(const float* __restrict__ x,
                                                 const float* __restrict__ w,
                                                 const float* __restrict__ bvec) {
    int tok = blockIdx.x;
    int b = tok >> 10, t = tok & 1023;
    const float* xp = x + (size_t)b * CC * TT + t;

    float vals[4];
    float s = 0.f, s2 = 0.f;
#pragma unroll
    for (int i = 0; i < 4; i++) {
        int c = threadIdx.x + i * 256;
        float v = __ldg(xp + (size_t)c * TT);
        vals[i] = v;
        s += v;
        s2 = fmaf(v, v, s2);
    }
#pragma unroll
    for (int o = 16; o; o >>= 1) {
        s  += __shfl_xor_sync(0xffffffffu, s,  o);
        s2 += __shfl_xor_sync(0xffffffffu, s2, o);
    }
    __shared__ float sh[16];
    int wp = threadIdx.x >> 5, ln = threadIdx.x & 31;
    if (ln == 0) { sh[wp] = s; sh[8 + wp] = s2; }
    __syncthreads();
    float S = 0.f, S2 = 0.f;
#pragma unroll
    for (int i = 0; i < 8; i++) { S += sh[i]; S2 += sh[8 + i]; }
    float mu  = S * (1.f / 1024.f);
    float var = S2 * (1.f / 1024.f) - mu * mu;
    float rs  = rsqrtf(var + 1e-5f);

    __half* op = e_xn + (size_t)tok * 2 * CC;
#pragma unroll
    for (int i = 0; i < 4; i++) {
        int c = threadIdx.x + i * 256;
        float v = (vals[i] - mu) * rs * w[c] + bvec[c];
        __half hi, lo; split2h(v, hi, lo);
        op[c] = hi; op[CC + c] = lo;
    }
}

template <int MODE>
__global__ __launch_bounds__(256) void convert2_kernel(const float* __restrict__ in,
                                                       __half* __restrict__ out,
                                                       int K, int halfTotal) {
    int i = blockIdx.x * 256 + threadIdx.x;
    if (i >= halfTotal) return;
    int K2 = K >> 1;
    int r = i / K2, k2 = i - r * K2;
    float2 v = *(const float2*)(in + (size_t)r * K + k2 * 2);
    __half h0, l0, h1, l1;
    split2h(v.x, h0, l0); split2h(v.y, h1, l1);
    uint32_t hh = ((uint32_t)__half_as_ushort(h1) << 16) | __half_as_ushort(h0);
    uint32_t ll = ((uint32_t)__half_as_ushort(l1) << 16) | __half_as_ushort(l0);
    uint32_t* o = (uint32_t*)(out + (size_t)r * 2 * K);
    if (MODE == 0) { o[k2] = hh; o[K2 + k2] = hh; }
    else           { o[k2] = hh; o[K2 + k2] = ll; }
}

// split-K reduce + fused dt_raw ext conversion
__global__ __launch_bounds__(256) void reduce_part_kernel() {
    int i = blockIdx.x * 256 + threadIdx.x;
    if (i >= TOKS * XDBL) return;
    float s = 0.f;
#pragma unroll
    for (int z = 0; z < SPLITK; z++) s += g_part[(size_t)z * TOKS * XDBL + i];
    g_xdbl[i] = s;
    int tok = i / XDBL, k = i - tok * XDBL;
    if (k < DTRANK) {
        __half hi, lo; split2h(s, hi, lo);
        __half* o = e_dtr + (size_t)tok * 2 * DTRANK;
        o[k] = hi; o[DTRANK + k] = lo;
    }
}

__global__ __launch_bounds__(256) void conv_silu_kernel(const float* __restrict__ conv_w,
                                                        const float* __restrict__ conv_b) {
    int idx = blockIdx.x * 256 + threadIdx.x;
    int d = idx & (DIN - 1);
    int tok = idx >> 11;
    int b = tok >> 10, t = tok & 1023;

    float w0 = conv_w[d * DCONV + 0];
    float w1 = conv_w[d * DCONV + 1];
    float w2 = conv_w[d * DCONV + 2];
    float w3 = conv_w[d * DCONV + 3];

    const float* xin = g_xz + (size_t)(b * TT) * (2 * DIN) + d;
    float v = conv_b[d];
    if (t >= 3) v = fmaf(w0, xin[(size_t)(t - 3) * (2 * DIN)], v);
    if (t >= 2) v = fmaf(w1, xin[(size_t)(t - 2) * (2 * DIN)], v);
    if (t >= 1) v = fmaf(w2, xin[(size_t)(t - 1) * (2 * DIN)], v);
    v = fmaf(w3, xin[(size_t)t * (2 * DIN)], v);

    float sig = 1.f / (1.f + __expf(-v));
    float o = v * sig;
    g_xc[idx] = o;
    __half hi, lo; split2h(o, hi, lo);
    __half* op = e_xc + (size_t)tok * 2 * DIN + d;
    op[0] = hi; op[DIN] = lo;
}

// ==================== windowed smem selective scan ====================
__global__ __launch_bounds__(512) void scan_kernel(const float* __restrict__ A_log,
                                                   const float* __restrict__ Dvec) {
    __shared__ __align__(16) float s_buf[2][4][SW * 32];  // [buf][dt,xc,z,bc]
    __shared__ float s_y[SW][32];

    int tid  = threadIdx.x;
    int lane = tid & 31, warp = tid >> 5;
    int chBase = blockIdx.x * 32;
    int b  = chBase >> 11;
    int d0 = chBase & (DIN - 1);
    int s  = lane & 15;
    int dloc = warp * 2 + (lane >> 4);
    int d = d0 + dloc;

    float A_s = -__expf(A_log[d * DSTATE + s]);
    float Dd  = Dvec[d];

    const float* dtG = g_dt   + (size_t)(b * TT) * DIN + d0;
    const float* xcG = g_xc   + (size_t)(b * TT) * DIN + d0;
    const float* zG  = g_xz   + (size_t)(b * TT) * (2 * DIN) + DIN + d0;
    const float* bcG = g_xdbl + (size_t)(b * TT) * XDBL + DTRANK;

    int lt  = tid >> 3;
    int seg = tid & 7;

    auto load_win = [&](int w, int buf) {
        int t0 = w * SW;
        const float* srcs[4] = {
            dtG + (size_t)(t0 + lt) * DIN       + seg * 4,
            xcG + (size_t)(t0 + lt) * DIN       + seg * 4,
            zG  + (size_t)(t0 + lt) * (2 * DIN) + seg * 4,
            bcG + (size_t)(t0 + lt) * XDBL      + seg * 4 };
#pragma unroll
        for (int a = 0; a < 4; a++)
            cp16(smem_u32(&s_buf[buf][a][lt * 32 + seg * 4]), srcs[a], true);
        asm volatile("cp.async.commit_group;\n");
    };

    constexpr int NW = TT / SW;
    load_win(0, 0);
    int buf = 0;
    float h = 0.f;

    for (int w = 0; w < NW; w++) {
        if (w + 1 < NW) {
            load_win(w + 1, buf ^ 1);
            asm volatile("cp.async.wait_group 1;\n");
        } else {
            asm volatile("cp.async.wait_group 0;\n");
        }
        __syncthreads();

        const float* fDT = s_buf[buf][0];
        const float* fXC = s_buf[buf][1];
        const float* fBC = s_buf[buf][3];
#pragma unroll 4
        for (int t = 0; t < SW; t++) {
            float dtv = fDT[t * 32 + dloc];
            float xv  = fXC[t * 32 + dloc];
            float Bv  = fBC[t * 32 + s];
            float Cv  = fBC[t * 32 + 16 + s];
            float dA  = __expf(dtv * A_s);
            h = fmaf(dA, h, dtv * Bv * xv);
            float p = h * Cv;
            p += __shfl_xor_sync(0xffffffffu, p, 8);
            p += __shfl_xor_sync(0xffffffffu, p, 4);
            p += __shfl_xor_sync(0xffffffffu, p, 2);
            p += __shfl_xor_sync(0xffffffffu, p, 1);
            if (s == 0) s_y[t][dloc] = fmaf(Dd, xv, p);
        }
        __syncthreads();

        const float* fZ = s_buf[buf][2];
        int t0 = w * SW;
#pragma unroll
        for (int k = 0; k < 4; k++) {
            int idx = tid + k * 512;
            int t = idx >> 5, dd = idx & 31;
            float yv = s_y[t][dd];
            float zv = fZ[t * 32 + dd];
            float sig = 1.f / (1.f + __expf(-zv));
            yv *= zv * sig;
            __half hi, lo; split2h(yv, hi, lo);
            __half* o = e_y + (size_t)(b * TT + t0 + t) * 2 * DIN + d0 + dd;
            o[0] = hi; o[DIN] = lo;
        }
        __syncthreads();
        buf ^= 1;
    }
}

// ==================== launch ====================
extern "C" void kernel_launch(void* const* d_in, const int* in_sizes, int n_in,
                              void* d_out, int out_size) {
    const float* x          = (const float*)d_in[0];
    const float* norm_w     = (const float*)d_in[1];
    const float* norm_b     = (const float*)d_in[2];
    const float* in_proj_w  = (const float*)d_in[3];
    const float* conv_w     = (const float*)d_in[4];
    const float* conv_b     = (const float*)d_in[5];
    const float* x_proj_w   = (const float*)d_in[6];
    const float* dt_proj_w  = (const float*)d_in[7];
    const float* dt_proj_b  = (const float*)d_in[8];
    const float* A_log      = (const float*)d_in[9];
    const float* Dvec       = (const float*)d_in[10];
    const float* out_proj_w = (const float*)d_in[11];
    float* out = (float*)d_out;

    float *xz, *xdbl, *dt, *part;
    __half *exn, *ew1, *exc, *ew2, *edtr, *ew3, *ey, *ew4;
    cudaGetSymbolAddress((void**)&xz,   g_xz);
    cudaGetSymbolAddress((void**)&xdbl, g_xdbl);
    cudaGetSymbolAddress((void**)&dt,   g_dt);
    cudaGetSymbolAddress((void**)&part, g_part);
    cudaGetSymbolAddress((void**)&exn,  e_xn);
    cudaGetSymbolAddress((void**)&ew1,  e_w1);
    cudaGetSymbolAddress((void**)&exc,  e_xc);
    cudaGetSymbolAddress((void**)&ew2,  e_w2);
    cudaGetSymbolAddress((void**)&edtr, e_dtr);
    cudaGetSymbolAddress((void**)&ew3,  e_w3);
    cudaGetSymbolAddress((void**)&ey,   e_y);
    cudaGetSymbolAddress((void**)&ew4,  e_w4);

    const int smem256 = 3 * (256 * 128 + 128 * 128);   // 147456
    const int smem128 = 3 * (128 * 128 + 128 * 128);   // 98304
    cudaFuncSetAttribute(gemm_mma<0, 256, 128>, cudaFuncAttributeMaxDynamicSharedMemorySize, smem256);
    cudaFuncSetAttribute(gemm_mma<1, 256, 128>, cudaFuncAttributeMaxDynamicSharedMemorySize, smem256);
    cudaFuncSetAttribute(gemm_mma<3, 128, 128>, cudaFuncAttributeMaxDynamicSharedMemorySize, smem128);
    cudaFuncSetAttribute(gemm_mma<2, 128, 128>, cudaFuncAttributeMaxDynamicSharedMemorySize, smem128);

    // 1. in_proj weight convert ([hi,hi])
    convert2_kernel<0><<<(2 * DIN * CC / 2 + 255) / 256, 256>>>(in_proj_w, ew1, CC, 2 * DIN * CC / 2);
    // 2. LayerNorm -> e_xn [hi,lo]
    ln_kernel<<<TOKS, 256>>>(x, norm_w, norm_b);
    // 3. out_proj weight convert
    convert2_kernel<0><<<(CC * DIN / 2 + 255) / 256, 256>>>(out_proj_w, ew4, DIN, CC * DIN / 2);
    // 4. in_proj GEMM  (PROFILED LAUNCH)  MT=256, Kext = 2*CC
    gemm_mma<0, 256, 128><<<dim3((2 * DIN) / 128, TOKS / 256), 256, smem256>>>(
        exn, 2 * CC, ew1, 2 * CC, xz, 2 * DIN, TOKS, 2 * DIN, 2 * CC, nullptr, nullptr);
    // 5. conv + SiLU -> g_xc + e_xc [hi,lo]
    conv_silu_kernel<<<(TOKS * DIN) / 256, 256>>>(conv_w, conv_b);
    // 6. x_proj weight convert
    convert2_kernel<0><<<(XDBL * DIN / 2 + 255) / 256, 256>>>(x_proj_w, ew2, DIN, XDBL * DIN / 2);
    // 7. x_proj split-K GEMM  Kext = 2*DIN = 4096, 16-way
    gemm_mma<3, 128, 128><<<dim3(1, TOKS / 128, SPLITK), 256, smem128>>>(
        exc, 2 * DIN, ew2, 2 * DIN, part, XDBL, TOKS, XDBL, 2 * DIN, nullptr, nullptr);
    // 8. reduce partials + fused dt_raw ext convert
    reduce_part_kernel<<<(TOKS * XDBL + 255) / 256, 256>>>();
    // 9. dt_proj weight convert
    convert2_kernel<0><<<(DIN * DTRANK / 2 + 255) / 256, 256>>>(dt_proj_w, ew3, DTRANK, DIN * DTRANK / 2);
    // 10. dt_proj + softplus  MT=256, Kext = 2*DTRANK = 128
    gemm_mma<1, 256, 128><<<dim3(DIN / 128, TOKS / 256), 256, smem256>>>(
        edtr, 2 * DTRANK, ew3, 2 * DTRANK, dt, DIN, TOKS, DIN, 2 * DTRANK, dt_proj_b, nullptr);
    // 11. selective scan + gate
    scan_kernel<<<(BB * DIN) / 32, 512>>>(A_log, Dvec);
    // 12. out_proj + residual transposed store  Kext = 2*DIN
    gemm_mma<2, 128, 128><<<dim3(CC / 128, TOKS / 128), 256, smem128>>>(
        ey, 2 * DIN, ew4, 2 * DIN, out, 0, TOKS, CC, 2 * DIN, nullptr, x);
}

// round 9
// speedup vs baseline: 1.3868x; 1.3868x over previous
#include <cuda_runtime.h>
#include <cuda_fp16.h>
#include <math.h>
#include <stdint.h>

// ---------------- problem constants ----------------
#define BB      2
#define CC      1024
#define TT      1024
#define TOKS    (BB * TT)          // 2048
#define DIN     2048
#define DSTATE  16
#define DTRANK  64
#define XDBL    96
#define DCONV   4
#define SPLITK  8
#define SW      64                 // scan window (t-steps)

// ---------------- fp32 scratch ----------------
__device__ float g_xz  [TOKS * 2 * DIN];
__device__ float g_xc  [TOKS * DIN];
__device__ float g_xdbl[TOKS * XDBL];
__device__ float g_dt  [TOKS * DIN];
__device__ float g_part[SPLITK * TOKS * XDBL];

// ---------------- fp16 operand scratch (plain fp16, no split) ----------------
__device__ __half e_xn [TOKS * CC];
__device__ __half e_w1 [2 * DIN * CC];
__device__ __half e_xc [TOKS * DIN];
__device__ __half e_w2 [XDBL * DIN];
__device__ __half e_dtr[TOKS * DTRANK];
__device__ __half e_w3 [DIN * DTRANK];
__device__ __half e_y  [TOKS * DIN];
__device__ __half e_w4 [CC * DIN];

// ==================== PTX helpers ====================
__device__ __forceinline__ uint32_t smem_u32(const void* p) {
    uint32_t a;
    asm("{ .reg .u64 t; cvta.to.shared.u64 t, %1; cvt.u32.u64 %0, t; }" : "=r"(a) : "l"(p));
    return a;
}
__device__ __forceinline__ void cp16(uint32_t dst, const void* src, bool pred) {
    int sz = pred ? 16 : 0;
    asm volatile("cp.async.cg.shared.global [%0], [%1], 16, %2;\n" :: "r"(dst), "l"(src), "r"(sz));
}
__device__ __forceinline__ void ldsm4(uint32_t& r0, uint32_t& r1, uint32_t& r2, uint32_t& r3,
                                      uint32_t addr) {
    asm volatile("ldmatrix.sync.aligned.m8n8.x4.shared.b16 {%0,%1,%2,%3}, [%4];"
                 : "=r"(r0), "=r"(r1), "=r"(r2), "=r"(r3) : "r"(addr));
}
__device__ __forceinline__ void mma16816(float* c, const uint32_t* a, const uint32_t* b) {
    asm volatile("mma.sync.aligned.m16n8k16.row.col.f32.f16.f16.f32 "
                 "{%0,%1,%2,%3}, {%4,%5,%6,%7}, {%8,%9}, {%0,%1,%2,%3};"
                 : "+f"(c[0]), "+f"(c[1]), "+f"(c[2]), "+f"(c[3])
                 : "r"(a[0]), "r"(a[1]), "r"(a[2]), "r"(a[3]), "r"(b[0]), "r"(b[1]));
}

// ==================== mma.sync fp16 GEMM (R6 config: 128x128, 2 CTA/SM) ====================
// C[M,N] = A[M,K] @ W[N,K]^T. K-tile 64, 3-stage cp.async ring.
// OP 0 plain | OP 1 softplus+bias | OP 2 transpose+residual | OP 3 split-K partials
template <int OP, int NT>
__global__ __launch_bounds__(256, 2)
void gemm_mma(const __half* __restrict__ A, int lda,
              const __half* __restrict__ W, int ldw,
              float* __restrict__ C, int ldc,
              int M, int N, int Kext,
              const float* __restrict__ bias,
              const float* __restrict__ resid) {
    constexpr int SA     = 128 * 128;       // bytes per A stage
    constexpr int SB     = NT * 128;
    constexpr int STAGE  = SA + SB;
    constexpr int WCOLS  = NT / 2;
    constexpr int NFR    = WCOLS / 8;
    constexpr int BLD    = WCOLS / 16;
    constexpr int BCHUNK = NT * 8 / 256;

    extern __shared__ float4 dyn4[];
    uint32_t base = smem_u32(dyn4);

    int tid = threadIdx.x, lane = tid & 31, warp = tid >> 5;
    int wm = warp & 3, wn = warp >> 2;
    int rowBase = blockIdx.y * 128, colBase = blockIdx.x * NT;

    int kStart = 0;
    if (OP == 3) {
        int ch = Kext / SPLITK;
        kStart = blockIdx.z * ch;
        Kext = ch;
        C += (size_t)blockIdx.z * M * ldc;
    }
    int nTiles = Kext / 64;

    float acc[2][NFR][4];
#pragma unroll
    for (int i = 0; i < 2; i++)
#pragma unroll
        for (int j = 0; j < NFR; j++)
#pragma unroll
            for (int e = 0; e < 4; e++) acc[i][j][e] = 0.f;

    auto load_tile = [&](int s, int kt) {
        uint32_t aB = base + s * STAGE, bB = aB + SA;
        int k0 = kStart + kt * 64;
#pragma unroll
        for (int i = 0; i < 4; i++) {
            int idx = tid + i * 256;
            int row = idx >> 3, c = idx & 7;
            cp16(aB + row * 128 + ((c ^ (row & 7)) << 4),
                 A + (size_t)(rowBase + row) * lda + k0 + c * 8, true);
        }
#pragma unroll
        for (int i = 0; i < BCHUNK; i++) {
            int idx = tid + i * 256;
            int row = idx >> 3, c = idx & 7;
            bool ok = (colBase + row) < N;
            cp16(bB + row * 128 + ((c ^ (row & 7)) << 4),
                 W + (ok ? (size_t)(colBase + row) * ldw : 0) + k0 + c * 8, ok);
        }
        asm volatile("cp.async.commit_group;\n");
    };

    load_tile(0, 0);
    if (nTiles > 1) load_tile(1, 1);

    for (int t = 0; t < nTiles; t++) {
        if (t + 1 >= nTiles) asm volatile("cp.async.wait_group 0;\n");
        else                 asm volatile("cp.async.wait_group 1;\n");
        __syncthreads();

        int s = t % 3;
        uint32_t aB = base + s * STAGE, bB = aB + SA;
#pragma unroll
        for (int ks = 0; ks < 4; ks++) {
            uint32_t afr[2][4];
#pragma unroll
            for (int mt = 0; mt < 2; mt++) {
                int row = wm * 32 + mt * 16 + (lane & 15);
                int unit = ks * 2 + (lane >> 4);
                ldsm4(afr[mt][0], afr[mt][1], afr[mt][2], afr[mt][3],
                      aB + row * 128 + ((unit ^ (row & 7)) << 4));
            }
            uint32_t bfr[NFR][2];
#pragma unroll
            for (int p = 0; p < BLD; p++) {
                int row = wn * WCOLS + p * 16 + (lane & 15);
                int unit = ks * 2 + (lane >> 4);
                uint32_t r0, r1, r2, r3;
                ldsm4(r0, r1, r2, r3, bB + row * 128 + ((unit ^ (row & 7)) << 4));
                bfr[2 * p][0] = r0; bfr[2 * p + 1][0] = r1;
                bfr[2 * p][1] = r2; bfr[2 * p + 1][1] = r3;
            }
#pragma unroll
            for (int mt = 0; mt < 2; mt++)
#pragma unroll
                for (int nt = 0; nt < NFR; nt++)
                    mma16816(acc[mt][nt], afr[mt], bfr[nt]);
        }
        if (t + 2 < nTiles) load_tile((t + 2) % 3, t + 2);
    }

#pragma unroll
    for (int mt = 0; mt < 2; mt++) {
        int m = rowBase + wm * 32 + mt * 16 + (lane >> 2);
#pragma unroll
        for (int nt = 0; nt < NFR; nt++) {
            int c0 = colBase + wn * WCOLS + nt * 8 + (lane & 3) * 2;
#pragma unroll
            for (int e = 0; e < 4; e++) {
                int mm = m + ((e >= 2) ? 8 : 0);
                int n = c0 + (e & 1);
                if (OP != 2 && n >= N) continue;
                float v = acc[mt][nt][e];
                if (OP == 0 || OP == 3) {
                    C[(size_t)mm * ldc + n] = v;
                } else if (OP == 1) {
                    v += bias[n];
                    C[(size_t)mm * ldc + n] = (v > 20.f) ? v : log1pf(__expf(v));
                } else {
                    int b = mm >> 10, tt2 = mm & 1023;
                    size_t oi = (size_t)b * CC * TT + (size_t)n * TT + tt2;
                    C[oi] = v + resid[oi];
                }
            }
        }
    }
}

// ==================== elementwise kernels ====================
__global__ __launch_bounds__(256) void ln_kernel(const float* __restrict__ x,
                                                 const float* __restrict__ w,
                                                 const float* __restrict__ bvec) {
    int tok = blockIdx.x;
    int b = tok >> 10, t = tok & 1023;
    const float* xp = x + (size_t)b * CC * TT + t;

    float vals[4];
    float s = 0.f, s2 = 0.f;
#pragma unroll
    for (int i = 0; i < 4; i++) {
        int c = threadIdx.x + i * 256;
        float v = __ldg(xp + (size_t)c * TT);
        vals[i] = v;
        s += v;
        s2 = fmaf(v, v, s2);
    }
#pragma unroll
    for (int o = 16; o; o >>= 1) {
        s  += __shfl_xor_sync(0xffffffffu, s,  o);
        s2 += __shfl_xor_sync(0xffffffffu, s2, o);
    }
    __shared__ float sh[16];
    int wp = threadIdx.x >> 5, ln = threadIdx.x & 31;
    if (ln == 0) { sh[wp] = s; sh[8 + wp] = s2; }
    __syncthreads();
    float S = 0.f, S2 = 0.f;
#pragma unroll
    for (int i = 0; i < 8; i++) { S += sh[i]; S2 += sh[8 + i]; }
    float mu  = S * (1.f / 1024.f);
    float var = S2 * (1.f / 1024.f) - mu * mu;
    float rs  = rsqrtf(var + 1e-5f);

    __half* op = e_xn + (size_t)tok * CC;
#pragma unroll
    for (int i = 0; i < 4; i++) {
        int c = threadIdx.x + i * 256;
        float v = (vals[i] - mu) * rs * w[c] + bvec[c];
        op[c] = __float2half_rn(v);
    }
}

// fp32 -> fp16 cast, 2 elems/thread
__global__ __launch_bounds__(256) void convert_kernel(const float* __restrict__ in,
                                                      __half* __restrict__ out,
                                                      int halfTotal) {
    int i = blockIdx.x * 256 + threadIdx.x;
    if (i >= halfTotal) return;
    float2 v = *(const float2*)(in + (size_t)i * 2);
    __half2 h = __floats2half2_rn(v.x, v.y);
    *(__half2*)(out + (size_t)i * 2) = h;
}

// split-K reduce + fused dt_raw fp16 conversion
__global__ __launch_bounds__(256) void reduce_part_kernel() {
    int i = blockIdx.x * 256 + threadIdx.x;
    if (i >= TOKS * XDBL) return;
    float s = 0.f;
#pragma unroll
    for (int z = 0; z < SPLITK; z++) s += g_part[(size_t)z * TOKS * XDBL + i];
    g_xdbl[i] = s;
    int tok = i / XDBL, k = i - tok * XDBL;
    if (k < DTRANK) e_dtr[(size_t)tok * DTRANK + k] = __float2half_rn(s);
}

__global__ __launch_bounds__(256) void conv_silu_kernel(const float* __restrict__ conv_w,
                                                        const float* __restrict__ conv_b) {
    int idx = blockIdx.x * 256 + threadIdx.x;
    int d = idx & (DIN - 1);
    int tok = idx >> 11;
    int b = tok >> 10, t = tok & 1023;

    float w0 = conv_w[d * DCONV + 0];
    float w1 = conv_w[d * DCONV + 1];
    float w2 = conv_w[d * DCONV + 2];
    float w3 = conv_w[d * DCONV + 3];

    const float* xin = g_xz + (size_t)(b * TT) * (2 * DIN) + d;
    float v = conv_b[d];
    if (t >= 3) v = fmaf(w0, xin[(size_t)(t - 3) * (2 * DIN)], v);
    if (t >= 2) v = fmaf(w1, xin[(size_t)(t - 2) * (2 * DIN)], v);
    if (t >= 1) v = fmaf(w2, xin[(size_t)(t - 1) * (2 * DIN)], v);
    v = fmaf(w3, xin[(size_t)t * (2 * DIN)], v);

    float sig = 1.f / (1.f + __expf(-v));
    float o = v * sig;
    g_xc[idx] = o;
    e_xc[idx] = __float2half_rn(o);
}

// ==================== windowed smem selective scan ====================
__global__ __launch_bounds__(512) void scan_kernel(const float* __restrict__ A_log,
                                                   const float* __restrict__ Dvec) {
    __shared__ __align__(16) float s_buf[2][4][SW * 32];  // [buf][dt,xc,z,bc]
    __shared__ float s_y[SW][32];

    int tid  = threadIdx.x;
    int lane = tid & 31, warp = tid >> 5;
    int chBase = blockIdx.x * 32;
    int b  = chBase >> 11;
    int d0 = chBase & (DIN - 1);
    int s  = lane & 15;
    int dloc = warp * 2 + (lane >> 4);
    int d = d0 + dloc;

    float A_s = -__expf(A_log[d * DSTATE + s]);
    float Dd  = Dvec[d];

    const float* dtG = g_dt   + (size_t)(b * TT) * DIN + d0;
    const float* xcG = g_xc   + (size_t)(b * TT) * DIN + d0;
    const float* zG  = g_xz   + (size_t)(b * TT) * (2 * DIN) + DIN + d0;
    const float* bcG = g_xdbl + (size_t)(b * TT) * XDBL + DTRANK;

    int lt  = tid >> 3;
    int seg = tid & 7;

    auto load_win = [&](int w, int buf) {
        int t0 = w * SW;
        const float* srcs[4] = {
            dtG + (size_t)(t0 + lt) * DIN       + seg * 4,
            xcG + (size_t)(t0 + lt) * DIN       + seg * 4,
            zG  + (size_t)(t0 + lt) * (2 * DIN) + seg * 4,
            bcG + (size_t)(t0 + lt) * XDBL      + seg * 4 };
#pragma unroll
        for (int a = 0; a < 4; a++)
            cp16(smem_u32(&s_buf[buf][a][lt * 32 + seg * 4]), srcs[a], true);
        asm volatile("cp.async.commit_group;\n");
    };

    constexpr int NW = TT / SW;
    load_win(0, 0);
    int buf = 0;
    float h = 0.f;

    for (int w = 0; w < NW; w++) {
        if (w + 1 < NW) {
            load_win(w + 1, buf ^ 1);
            asm volatile("cp.async.wait_group 1;\n");
        } else {
            asm volatile("cp.async.wait_group 0;\n");
        }
        __syncthreads();

        const float* fDT = s_buf[buf][0];
        const float* fXC = s_buf[buf][1];
        const float* fBC = s_buf[buf][3];
#pragma unroll 4
        for (int t = 0; t < SW; t++) {
            float dtv = fDT[t * 32 + dloc];
            float xv  = fXC[t * 32 + dloc];
            float Bv  = fBC[t * 32 + s];
            float Cv  = fBC[t * 32 + 16 + s];
            float dA  = __expf(dtv * A_s);
            h = fmaf(dA, h, dtv * Bv * xv);
            float p = h * Cv;
            p += __shfl_xor_sync(0xffffffffu, p, 8);
            p += __shfl_xor_sync(0xffffffffu, p, 4);
            p += __shfl_xor_sync(0xffffffffu, p, 2);
            p += __shfl_xor_sync(0xffffffffu, p, 1);
            if (s == 0) s_y[t][dloc] = fmaf(Dd, xv, p);
        }
        __syncthreads();

        const float* fZ = s_buf[buf][2];
        int t0 = w * SW;
#pragma unroll
        for (int k = 0; k < 4; k++) {
            int idx = tid + k * 512;
            int t = idx >> 5, dd = idx & 31;
            float yv = s_y[t][dd];
            float zv = fZ[t * 32 + dd];
            float sig = 1.f / (1.f + __expf(-zv));
            yv *= zv * sig;
            e_y[(size_t)(b * TT + t0 + t) * DIN + d0 + dd] = __float2half_rn(yv);
        }
        __syncthreads();
        buf ^= 1;
    }
}

// ==================== launch ====================
extern "C" void kernel_launch(void* const* d_in, const int* in_sizes, int n_in,
                              void* d_out, int out_size) {
    const float* x          = (const float*)d_in[0];
    const float* norm_w     = (const float*)d_in[1];
    const float* norm_b     = (const float*)d_in[2];
    const float* in_proj_w  = (const float*)d_in[3];
    const float* conv_w     = (const float*)d_in[4];
    const float* conv_b     = (const float*)d_in[5];
    const float* x_proj_w   = (const float*)d_in[6];
    const float* dt_proj_w  = (const float*)d_in[7];
    const float* dt_proj_b  = (const float*)d_in[8];
    const float* A_log      = (const float*)d_in[9];
    const float* Dvec       = (const float*)d_in[10];
    const float* out_proj_w = (const float*)d_in[11];
    float* out = (float*)d_out;

    float *xz, *xdbl, *dt, *part;
    __half *exn, *ew1, *exc, *ew2, *edtr, *ew3, *ey, *ew4;
    cudaGetSymbolAddress((void**)&xz,   g_xz);
    cudaGetSymbolAddress((void**)&xdbl, g_xdbl);
    cudaGetSymbolAddress((void**)&dt,   g_dt);
    cudaGetSymbolAddress((void**)&part, g_part);
    cudaGetSymbolAddress((void**)&exn,  e_xn);
    cudaGetSymbolAddress((void**)&ew1,  e_w1);
    cudaGetSymbolAddress((void**)&exc,  e_xc);
    cudaGetSymbolAddress((void**)&ew2,  e_w2);
    cudaGetSymbolAddress((void**)&edtr, e_dtr);
    cudaGetSymbolAddress((void**)&ew3,  e_w3);
    cudaGetSymbolAddress((void**)&ey,   e_y);
    cudaGetSymbolAddress((void**)&ew4,  e_w4);

    const int smem128 = 3 * (128 * 128 + 128 * 128);   // 98304
    cudaFuncSetAttribute(gemm_mma<0, 128>, cudaFuncAttributeMaxDynamicSharedMemorySize, smem128);
    cudaFuncSetAttribute(gemm_mma<1, 128>, cudaFuncAttributeMaxDynamicSharedMemorySize, smem128);
    cudaFuncSetAttribute(gemm_mma<3, 128>, cudaFuncAttributeMaxDynamicSharedMemorySize, smem128);
    cudaFuncSetAttribute(gemm_mma<2, 128>, cudaFuncAttributeMaxDynamicSharedMemorySize, smem128);

    // 1. in_proj weight convert (plain fp16)
    convert_kernel<<<(2 * DIN * CC / 2 + 255) / 256, 256>>>(in_proj_w, ew1, 2 * DIN * CC / 2);
    // 2. LayerNorm -> e_xn fp16
    ln_kernel<<<TOKS, 256>>>(x, norm_w, norm_b);
    // 3. out_proj weight convert
    convert_kernel<<<(CC * DIN / 2 + 255) / 256, 256>>>(out_proj_w, ew4, CC * DIN / 2);
    // 4. in_proj GEMM  (PROFILED LAUNCH)  K = CC = 1024
    gemm_mma<0, 128><<<dim3((2 * DIN) / 128, TOKS / 128), 256, smem128>>>(
        exn, CC, ew1, CC, xz, 2 * DIN, TOKS, 2 * DIN, CC, nullptr, nullptr);
    // 5. conv + SiLU -> g_xc + e_xc
    conv_silu_kernel<<<(TOKS * DIN) / 256, 256>>>(conv_w, conv_b);
    // 6. x_proj weight convert
    convert_kernel<<<(XDBL * DIN / 2 + 255) / 256, 256>>>(x_proj_w, ew2, XDBL * DIN / 2);
    // 7. x_proj split-K GEMM  K = DIN = 2048, 8-way -> 256 per split
    gemm_mma<3, 128><<<dim3(1, TOKS / 128, SPLITK), 256, smem128>>>(
        exc, DIN, ew2, DIN, part, XDBL, TOKS, XDBL, DIN, nullptr, nullptr);
    // 8. reduce partials + fused dt_raw fp16 convert
    reduce_part_kernel<<<(TOKS * XDBL + 255) / 256, 256>>>();
    // 9. dt_proj weight convert
    convert_kernel<<<(DIN * DTRANK / 2 + 255) / 256, 256>>>(dt_proj_w, ew3, DIN * DTRANK / 2);
    // 10. dt_proj + softplus  K = DTRANK = 64 (single K-tile)
    gemm_mma<1, 128><<<dim3(DIN / 128, TOKS / 128), 256, smem128>>>(
        edtr, DTRANK, ew3, DTRANK, dt, DIN, TOKS, DIN, DTRANK, dt_proj_b, nullptr);
    // 11. selective scan + gate
    scan_kernel<<<(BB * DIN) / 32, 512>>>(A_log, Dvec);
    // 12. out_proj + residual transposed store  K = DIN
    gemm_mma<2, 128><<<dim3(CC / 128, TOKS / 128), 256, smem128>>>(
        ey, DIN, ew4, DIN, out, 0, TOKS, CC, DIN, nullptr, x);
}

// round 10
// speedup vs baseline: 1.4383x; 1.0371x over previous
#include <cuda_runtime.h>
#include <cuda_fp16.h>
#include <math.h>
#include <stdint.h>

// ---------------- problem constants ----------------
#define BB      2
#define CC      1024
#define TT      1024
#define TOKS    (BB * TT)          // 2048
#define DIN     2048
#define DSTATE  16
#define DTRANK  64
#define XDBL    96
#define DCONV   4
#define SPLITK  8
#define SW      64                 // scan window (t-steps)

// ---------------- fp32 scratch ----------------
__device__ float g_xz  [TOKS * 2 * DIN];
__device__ float g_xc  [TOKS * DIN];
__device__ float g_xdbl[TOKS * XDBL];
__device__ float g_dt  [TOKS * DIN];
__device__ float g_part[SPLITK * TOKS * XDBL];

// ---------------- fp16 operand scratch ----------------
__device__ __half e_xn [TOKS * CC];
__device__ __half e_w1 [2 * DIN * CC];
__device__ __half e_xc [TOKS * DIN];
__device__ __half e_w2 [XDBL * DIN];
__device__ __half e_dtr[TOKS * DTRANK];
__device__ __half e_w3 [DIN * DTRANK];
__device__ __half e_y  [TOKS * DIN];
__device__ __half e_w4 [CC * DIN];

// ==================== PTX helpers ====================
__device__ __forceinline__ uint32_t smem_u32(const void* p) {
    uint32_t a;
    asm("{ .reg .u64 t; cvta.to.shared.u64 t, %1; cvt.u32.u64 %0, t; }" : "=r"(a) : "l"(p));
    return a;
}
__device__ __forceinline__ void cp16(uint32_t dst, const void* src, bool pred) {
    int sz = pred ? 16 : 0;
    asm volatile("cp.async.cg.shared.global [%0], [%1], 16, %2;\n" :: "r"(dst), "l"(src), "r"(sz));
}
__device__ __forceinline__ void ldsm4(uint32_t& r0, uint32_t& r1, uint32_t& r2, uint32_t& r3,
                                      uint32_t addr) {
    asm volatile("ldmatrix.sync.aligned.m8n8.x4.shared.b16 {%0,%1,%2,%3}, [%4];"
                 : "=r"(r0), "=r"(r1), "=r"(r2), "=r"(r3) : "r"(addr));
}
__device__ __forceinline__ void mma16816(float* c, const uint32_t* a, const uint32_t* b) {
    asm volatile("mma.sync.aligned.m16n8k16.row.col.f32.f16.f16.f32 "
                 "{%0,%1,%2,%3}, {%4,%5,%6,%7}, {%8,%9}, {%0,%1,%2,%3};"
                 : "+f"(c[0]), "+f"(c[1]), "+f"(c[2]), "+f"(c[3])
                 : "r"(a[0]), "r"(a[1]), "r"(a[2]), "r"(a[3]), "r"(b[0]), "r"(b[1]));
}

// ==================== mma.sync fp16 GEMM ====================
// C[M,N] = A[M,K] @ W[N,K]^T. 128x NT tile, K-tile 64, 3-stage cp.async ring.
// OP 0 plain | OP 1 softplus+bias | OP 2 smem-staged transpose+residual | OP 3 split-K partials
template <int OP, int NT>
__global__ __launch_bounds__(256, 2)
void gemm_mma(const __half* __restrict__ A, int lda,
              const __half* __restrict__ W, int ldw,
              float* __restrict__ C, int ldc,
              int M, int N, int Kext,
              const float* __restrict__ bias,
              const float* __restrict__ resid) {
    constexpr int SA     = 128 * 128;
    constexpr int SB     = NT * 128;
    constexpr int STAGE  = SA + SB;
    constexpr int WCOLS  = NT / 2;
    constexpr int NFR    = WCOLS / 8;
    constexpr int BLD    = WCOLS / 16;
    constexpr int BCHUNK = NT * 8 / 256;

    extern __shared__ float4 dyn4[];
    uint32_t base = smem_u32(dyn4);

    int tid = threadIdx.x, lane = tid & 31, warp = tid >> 5;
    int wm = warp & 3, wn = warp >> 2;
    int rowBase = blockIdx.y * 128, colBase = blockIdx.x * NT;

    int kStart = 0;
    if (OP == 3) {
        int ch = Kext / SPLITK;
        kStart = blockIdx.z * ch;
        Kext = ch;
        C += (size_t)blockIdx.z * M * ldc;
    }
    int nTiles = Kext / 64;

    float acc[2][NFR][4];
#pragma unroll
    for (int i = 0; i < 2; i++)
#pragma unroll
        for (int j = 0; j < NFR; j++)
#pragma unroll
            for (int e = 0; e < 4; e++) acc[i][j][e] = 0.f;

    auto load_tile = [&](int s, int kt) {
        uint32_t aB = base + s * STAGE, bB = aB + SA;
        int k0 = kStart + kt * 64;
#pragma unroll
        for (int i = 0; i < 4; i++) {
            int idx = tid + i * 256;
            int row = idx >> 3, c = idx & 7;
            cp16(aB + row * 128 + ((c ^ (row & 7)) << 4),
                 A + (size_t)(rowBase + row) * lda + k0 + c * 8, true);
        }
#pragma unroll
        for (int i = 0; i < BCHUNK; i++) {
            int idx = tid + i * 256;
            int row = idx >> 3, c = idx & 7;
            bool ok = (colBase + row) < N;
            cp16(bB + row * 128 + ((c ^ (row & 7)) << 4),
                 W + (ok ? (size_t)(colBase + row) * ldw : 0) + k0 + c * 8, ok);
        }
        asm volatile("cp.async.commit_group;\n");
    };

    load_tile(0, 0);
    if (nTiles > 1) load_tile(1, 1);

    for (int t = 0; t < nTiles; t++) {
        if (t + 1 >= nTiles) asm volatile("cp.async.wait_group 0;\n");
        else                 asm volatile("cp.async.wait_group 1;\n");
        __syncthreads();

        int s = t % 3;
        uint32_t aB = base + s * STAGE, bB = aB + SA;
#pragma unroll
        for (int ks = 0; ks < 4; ks++) {
            uint32_t afr[2][4];
#pragma unroll
            for (int mt = 0; mt < 2; mt++) {
                int row = wm * 32 + mt * 16 + (lane & 15);
                int unit = ks * 2 + (lane >> 4);
                ldsm4(afr[mt][0], afr[mt][1], afr[mt][2], afr[mt][3],
                      aB + row * 128 + ((unit ^ (row & 7)) << 4));
            }
            uint32_t bfr[NFR][2];
#pragma unroll
            for (int p = 0; p < BLD; p++) {
                int row = wn * WCOLS + p * 16 + (lane & 15);
                int unit = ks * 2 + (lane >> 4);
                uint32_t r0, r1, r2, r3;
                ldsm4(r0, r1, r2, r3, bB + row * 128 + ((unit ^ (row & 7)) << 4));
                bfr[2 * p][0] = r0; bfr[2 * p + 1][0] = r1;
                bfr[2 * p][1] = r2; bfr[2 * p + 1][1] = r3;
            }
#pragma unroll
            for (int mt = 0; mt < 2; mt++)
#pragma unroll
                for (int nt = 0; nt < NFR; nt++)
                    mma16816(acc[mt][nt], afr[mt], bfr[nt]);
        }
        if (t + 2 < nTiles) load_tile((t + 2) % 3, t + 2);
    }

    if (OP == 2) {
        // smem-staged transpose: stage [n_local][m_local], then coalesced rows.
        __syncthreads();                  // stage buffers done being read
        float* st = (float*)dyn4;
        const int PITCH = 132;            // conflict-free store pattern
#pragma unroll
        for (int mt = 0; mt < 2; mt++)
#pragma unroll
            for (int nt = 0; nt < NFR; nt++)
#pragma unroll
                for (int e = 0; e < 4; e++) {
                    int ml = wm * 32 + mt * 16 + (lane >> 2) + ((e >= 2) ? 8 : 0);
                    int nl = wn * WCOLS + nt * 8 + (lane & 3) * 2 + (e & 1);
                    st[nl * PITCH + ml] = acc[mt][nt][e];
                }
        __syncthreads();
        int b = rowBase >> 10, t0 = rowBase & 1023;
        for (int r = warp; r < 128; r += 8) {
            float4 v = *(float4*)&st[r * PITCH + lane * 4];
            size_t oi = (size_t)b * CC * TT + (size_t)(colBase + r) * TT + t0 + lane * 4;
            float4 rv = *(const float4*)(resid + oi);
            v.x += rv.x; v.y += rv.y; v.z += rv.z; v.w += rv.w;
            *(float4*)(C + oi) = v;
        }
    } else {
#pragma unroll
        for (int mt = 0; mt < 2; mt++) {
            int m = rowBase + wm * 32 + mt * 16 + (lane >> 2);
#pragma unroll
            for (int nt = 0; nt < NFR; nt++) {
                int c0 = colBase + wn * WCOLS + nt * 8 + (lane & 3) * 2;
#pragma unroll
                for (int e = 0; e < 4; e++) {
                    int mm = m + ((e >= 2) ? 8 : 0);
                    int n = c0 + (e & 1);
                    if (n >= N) continue;
                    float v = acc[mt][nt][e];
                    if (OP == 0 || OP == 3) {
                        C[(size_t)mm * ldc + n] = v;
                    } else {  // OP == 1
                        v += bias[n];
                        C[(size_t)mm * ldc + n] = (v > 20.f) ? v : log1pf(__expf(v));
                    }
                }
            }
        }
    }
}

// ==================== elementwise kernels ====================
__global__ __launch_bounds__(256) void ln_kernel(const float* __restrict__ x,
                                                 const float* __restrict__ w,
                                                 const float* __restrict__ bvec) {
    int tok = blockIdx.x;
    int b = tok >> 10, t = tok & 1023;
    const float* xp = x + (size_t)b * CC * TT + t;

    float vals[4];
    float s = 0.f, s2 = 0.f;
#pragma unroll
    for (int i = 0; i < 4; i++) {
        int c = threadIdx.x + i * 256;
        float v = __ldg(xp + (size_t)c * TT);
        vals[i] = v;
        s += v;
        s2 = fmaf(v, v, s2);
    }
#pragma unroll
    for (int o = 16; o; o >>= 1) {
        s  += __shfl_xor_sync(0xffffffffu, s,  o);
        s2 += __shfl_xor_sync(0xffffffffu, s2, o);
    }
    __shared__ float sh[16];
    int wp = threadIdx.x >> 5, ln = threadIdx.x & 31;
    if (ln == 0) { sh[wp] = s; sh[8 + wp] = s2; }
    __syncthreads();
    float S = 0.f, S2 = 0.f;
#pragma unroll
    for (int i = 0; i < 8; i++) { S += sh[i]; S2 += sh[8 + i]; }
    float mu  = S * (1.f / 1024.f);
    float var = S2 * (1.f / 1024.f) - mu * mu;
    float rs  = rsqrtf(var + 1e-5f);

    __half* op = e_xn + (size_t)tok * CC;
#pragma unroll
    for (int i = 0; i < 4; i++) {
        int c = threadIdx.x + i * 256;
        float v = (vals[i] - mu) * rs * w[c] + bvec[c];
        op[c] = __float2half_rn(v);
    }
}

// single-launch fp32->fp16 cast over 4 segments
struct Cvt4 {
    const float* in0; const float* in1; const float* in2; const float* in3;
    __half* out0; __half* out1; __half* out2; __half* out3;
    int c0, c1, c2, c3;   // cumulative half-counts
};
__global__ __launch_bounds__(256) void convert4_kernel(Cvt4 c) {
    int i = blockIdx.x * 256 + threadIdx.x;
    if (i >= c.c3) return;
    const float* in; __half* out; int j;
    if (i < c.c0)      { in = c.in0; out = c.out0; j = i; }
    else if (i < c.c1) { in = c.in1; out = c.out1; j = i - c.c0; }
    else if (i < c.c2) { in = c.in2; out = c.out2; j = i - c.c1; }
    else               { in = c.in3; out = c.out3; j = i - c.c2; }
    float2 v = *(const float2*)(in + (size_t)j * 2);
    *(__half2*)(out + (size_t)j * 2) = __floats2half2_rn(v.x, v.y);
}

// split-K reduce + fused dt_raw fp16 conversion
__global__ __launch_bounds__(256) void reduce_part_kernel() {
    int i = blockIdx.x * 256 + threadIdx.x;
    if (i >= TOKS * XDBL) return;
    float s = 0.f;
#pragma unroll
    for (int z = 0; z < SPLITK; z++) s += g_part[(size_t)z * TOKS * XDBL + i];
    g_xdbl[i] = s;
    int tok = i / XDBL, k = i - tok * XDBL;
    if (k < DTRANK) e_dtr[(size_t)tok * DTRANK + k] = __float2half_rn(s);
}

// conv+SiLU: each thread does 4 consecutive t for one d (7 loads / 4 outputs)
__global__ __launch_bounds__(256) void conv_silu_kernel(const float* __restrict__ conv_w,
                                                        const float* __restrict__ conv_b) {
    int i = blockIdx.x * 256 + threadIdx.x;     // (tgroup, d)
    int d = i & (DIN - 1);
    int tg = i >> 11;                           // 0..511
    int b = tg >> 8;
    int t0 = (tg & 255) * 4;

    float w0 = conv_w[d * DCONV + 0];
    float w1 = conv_w[d * DCONV + 1];
    float w2 = conv_w[d * DCONV + 2];
    float w3 = conv_w[d * DCONV + 3];
    float bias = conv_b[d];

    const float* xin = g_xz + (size_t)(b * TT) * (2 * DIN) + d;
    float xv[7];
#pragma unroll
    for (int j = 0; j < 7; j++) {
        int t = t0 - 3 + j;
        xv[j] = (t >= 0) ? xin[(size_t)t * (2 * DIN)] : 0.f;
    }
#pragma unroll
    for (int k = 0; k < 4; k++) {
        float v = bias;
        v = fmaf(w0, xv[k],     v);
        v = fmaf(w1, xv[k + 1], v);
        v = fmaf(w2, xv[k + 2], v);
        v = fmaf(w3, xv[k + 3], v);
        float sig = 1.f / (1.f + __expf(-v));
        float o = v * sig;
        size_t idx = (size_t)(b * TT + t0 + k) * DIN + d;
        g_xc[idx] = o;
        e_xc[idx] = __float2half_rn(o);
    }
}

// ==================== windowed smem selective scan ====================
__global__ __launch_bounds__(512) void scan_kernel(const float* __restrict__ A_log,
                                                   const float* __restrict__ Dvec) {
    __shared__ __align__(16) float s_buf[2][4][SW * 32];  // [buf][dt,xc,z,bc]
    __shared__ float s_y[SW][32];

    int tid  = threadIdx.x;
    int lane = tid & 31, warp = tid >> 5;
    int chBase = blockIdx.x * 32;
    int b  = chBase >> 11;
    int d0 = chBase & (DIN - 1);
    int s  = lane & 15;
    int dloc = warp * 2 + (lane >> 4);
    int d = d0 + dloc;

    float A_s = -__expf(A_log[d * DSTATE + s]);
    float Dd  = Dvec[d];

    const float* dtG = g_dt   + (size_t)(b * TT) * DIN + d0;
    const float* xcG = g_xc   + (size_t)(b * TT) * DIN + d0;
    const float* zG  = g_xz   + (size_t)(b * TT) * (2 * DIN) + DIN + d0;
    const float* bcG = g_xdbl + (size_t)(b * TT) * XDBL + DTRANK;

    int lt  = tid >> 3;
    int seg = tid & 7;

    auto load_win = [&](int w, int buf) {
        int t0 = w * SW;
        const float* srcs[4] = {
            dtG + (size_t)(t0 + lt) * DIN       + seg * 4,
            xcG + (size_t)(t0 + lt) * DIN       + seg * 4,
            zG  + (size_t)(t0 + lt) * (2 * DIN) + seg * 4,
            bcG + (size_t)(t0 + lt) * XDBL      + seg * 4 };
#pragma unroll
        for (int a = 0; a < 4; a++)
            cp16(smem_u32(&s_buf[buf][a][lt * 32 + seg * 4]), srcs[a], true);
        asm volatile("cp.async.commit_group;\n");
    };

    constexpr int NW = TT / SW;
    load_win(0, 0);
    int buf = 0;
    float h = 0.f;

    for (int w = 0; w < NW; w++) {
        if (w + 1 < NW) {
            load_win(w + 1, buf ^ 1);
            asm volatile("cp.async.wait_group 1;\n");
        } else {
            asm volatile("cp.async.wait_group 0;\n");
        }
        __syncthreads();

        const float* fDT = s_buf[buf][0];
        const float* fXC = s_buf[buf][1];
        const float* fBC = s_buf[buf][3];
#pragma unroll 4
        for (int t = 0; t < SW; t++) {
            float dtv = fDT[t * 32 + dloc];
            float xv  = fXC[t * 32 + dloc];
            float Bv  = fBC[t * 32 + s];
            float Cv  = fBC[t * 32 + 16 + s];
            float dA  = __expf(dtv * A_s);
            h = fmaf(dA, h, dtv * Bv * xv);
            float p = h * Cv;
            p += __shfl_xor_sync(0xffffffffu, p, 8);
            p += __shfl_xor_sync(0xffffffffu, p, 4);
            p += __shfl_xor_sync(0xffffffffu, p, 2);
            p += __shfl_xor_sync(0xffffffffu, p, 1);
            if (s == 0) s_y[t][dloc] = fmaf(Dd, xv, p);
        }
        __syncthreads();

        const float* fZ = s_buf[buf][2];
        int t0 = w * SW;
#pragma unroll
        for (int k = 0; k < 4; k++) {
            int idx = tid + k * 512;
            int t = idx >> 5, dd = idx & 31;
            float yv = s_y[t][dd];
            float zv = fZ[t * 32 + dd];
            float sig = 1.f / (1.f + __expf(-zv));
            yv *= zv * sig;
            e_y[(size_t)(b * TT + t0 + t) * DIN + d0 + dd] = __float2half_rn(yv);
        }
        __syncthreads();
        buf ^= 1;
    }
}

// ==================== launch ====================
extern "C" void kernel_launch(void* const* d_in, const int* in_sizes, int n_in,
                              void* d_out, int out_size) {
    const float* x          = (const float*)d_in[0];
    const float* norm_w     = (const float*)d_in[1];
    const float* norm_b     = (const float*)d_in[2];
    const float* in_proj_w  = (const float*)d_in[3];
    const float* conv_w     = (const float*)d_in[4];
    const float* conv_b     = (const float*)d_in[5];
    const float* x_proj_w   = (const float*)d_in[6];
    const float* dt_proj_w  = (const float*)d_in[7];
    const float* dt_proj_b  = (const float*)d_in[8];
    const float* A_log      = (const float*)d_in[9];
    const float* Dvec       = (const float*)d_in[10];
    const float* out_proj_w = (const float*)d_in[11];
    float* out = (float*)d_out;

    float *xz, *xdbl, *dt, *part;
    __half *exn, *ew1, *exc, *ew2, *edtr, *ew3, *ey, *ew4;
    cudaGetSymbolAddress((void**)&xz,   g_xz);
    cudaGetSymbolAddress((void**)&xdbl, g_xdbl);
    cudaGetSymbolAddress((void**)&dt,   g_dt);
    cudaGetSymbolAddress((void**)&part, g_part);
    cudaGetSymbolAddress((void**)&exn,  e_xn);
    cudaGetSymbolAddress((void**)&ew1,  e_w1);
    cudaGetSymbolAddress((void**)&exc,  e_xc);
    cudaGetSymbolAddress((void**)&ew2,  e_w2);
    cudaGetSymbolAddress((void**)&edtr, e_dtr);
    cudaGetSymbolAddress((void**)&ew3,  e_w3);
    cudaGetSymbolAddress((void**)&ey,   e_y);
    cudaGetSymbolAddress((void**)&ew4,  e_w4);

    const int smem128 = 3 * (128 * 128 + 128 * 128);   // 98304 (also covers OP2 stage 67.6KB)
    cudaFuncSetAttribute(gemm_mma<0, 128>, cudaFuncAttributeMaxDynamicSharedMemorySize, smem128);
    cudaFuncSetAttribute(gemm_mma<1, 128>, cudaFuncAttributeMaxDynamicSharedMemorySize, smem128);
    cudaFuncSetAttribute(gemm_mma<3, 128>, cudaFuncAttributeMaxDynamicSharedMemorySize, smem128);
    cudaFuncSetAttribute(gemm_mma<2, 128>, cudaFuncAttributeMaxDynamicSharedMemorySize, smem128);

    // 1. all weight converts in one launch
    Cvt4 cv;
    cv.in0 = in_proj_w;  cv.out0 = ew1;
    cv.in1 = out_proj_w; cv.out1 = ew4;
    cv.in2 = x_proj_w;   cv.out2 = ew2;
    cv.in3 = dt_proj_w;  cv.out3 = ew3;
    int n0 = 2 * DIN * CC / 2, n1 = CC * DIN / 2, n2 = XDBL * DIN / 2, n3 = DIN * DTRANK / 2;
    cv.c0 = n0; cv.c1 = n0 + n1; cv.c2 = n0 + n1 + n2; cv.c3 = n0 + n1 + n2 + n3;
    convert4_kernel<<<(cv.c3 + 255) / 256, 256>>>(cv);
    // 2. LayerNorm -> e_xn fp16
    ln_kernel<<<TOKS, 256>>>(x, norm_w, norm_b);
    // 3. in_proj GEMM  K = CC
    gemm_mma<0, 128><<<dim3((2 * DIN) / 128, TOKS / 128), 256, smem128>>>(
        exn, CC, ew1, CC, xz, 2 * DIN, TOKS, 2 * DIN, CC, nullptr, nullptr);
    // 4. conv + SiLU  (PROFILED LAUNCH)
    conv_silu_kernel<<<(TOKS / 4) * DIN / 256, 256>>>(conv_w, conv_b);
    // 5. x_proj split-K GEMM  K = DIN, 8-way
    gemm_mma<3, 128><<<dim3(1, TOKS / 128, SPLITK), 256, smem128>>>(
        exc, DIN, ew2, DIN, part, XDBL, TOKS, XDBL, DIN, nullptr, nullptr);
    // 6. reduce partials + fused dt_raw fp16 convert
    reduce_part_kernel<<<(TOKS * XDBL + 255) / 256, 256>>>();
    // 7. dt_proj + softplus  K = DTRANK
    gemm_mma<1, 128><<<dim3(DIN / 128, TOKS / 128), 256, smem128>>>(
        edtr, DTRANK, ew3, DTRANK, dt, DIN, TOKS, DIN, DTRANK, dt_proj_b, nullptr);
    // 8. selective scan + gate
    scan_kernel<<<(BB * DIN) / 32, 512>>>(A_log, Dvec);
    // 9. out_proj + residual, smem-staged transposed store  K = DIN
    gemm_mma<2, 128><<<dim3(CC / 128, TOKS / 128), 256, smem128>>>(
        ey, DIN, ew4, DIN, out, 0, TOKS, CC, DIN, nullptr, x);
}

// round 11
// speedup vs baseline: 1.4915x; 1.0370x over previous
#include <cuda_runtime.h>
#include <cuda_fp16.h>
#include <math.h>
#include <stdint.h>

// ---------------- problem constants ----------------
#define BB      2
#define CC      1024
#define TT      1024
#define TOKS    (BB * TT)          // 2048
#define DIN     2048
#define DSTATE  16
#define DTRANK  64
#define XDBL    96
#define DCONV   4
#define SPLITK  8
#define SW      64                 // scan window (t-steps)

// ---------------- fp32 scratch ----------------
__device__ float g_xdbl[TOKS * XDBL];
__device__ float g_part[SPLITK * TOKS * XDBL];

// ---------------- fp16 scratch ----------------
__device__ __half e_xn [TOKS * CC];
__device__ __half e_w1 [2 * DIN * CC];
__device__ __half e_xz [TOKS * 2 * DIN];     // in_proj out (x_in | z), fp16
__device__ __half e_xc [TOKS * DIN];         // conv+silu out
__device__ __half e_w2 [XDBL * DIN];
__device__ __half e_dtr[TOKS * DTRANK];
__device__ __half e_w3 [DIN * DTRANK];
__device__ __half e_dt [TOKS * DIN];         // softplus(dt), fp16
__device__ __half e_y  [TOKS * DIN];
__device__ __half e_w4 [CC * DIN];

// ==================== PTX helpers ====================
__device__ __forceinline__ uint32_t smem_u32(const void* p) {
    uint32_t a;
    asm("{ .reg .u64 t; cvta.to.shared.u64 t, %1; cvt.u32.u64 %0, t; }" : "=r"(a) : "l"(p));
    return a;
}
__device__ __forceinline__ void cp16(uint32_t dst, const void* src, bool pred) {
    int sz = pred ? 16 : 0;
    asm volatile("cp.async.cg.shared.global [%0], [%1], 16, %2;\n" :: "r"(dst), "l"(src), "r"(sz));
}
__device__ __forceinline__ void ldsm4(uint32_t& r0, uint32_t& r1, uint32_t& r2, uint32_t& r3,
                                      uint32_t addr) {
    asm volatile("ldmatrix.sync.aligned.m8n8.x4.shared.b16 {%0,%1,%2,%3}, [%4];"
                 : "=r"(r0), "=r"(r1), "=r"(r2), "=r"(r3) : "r"(addr));
}
__device__ __forceinline__ void mma16816(float* c, const uint32_t* a, const uint32_t* b) {
    asm volatile("mma.sync.aligned.m16n8k16.row.col.f32.f16.f16.f32 "
                 "{%0,%1,%2,%3}, {%4,%5,%6,%7}, {%8,%9}, {%0,%1,%2,%3};"
                 : "+f"(c[0]), "+f"(c[1]), "+f"(c[2]), "+f"(c[3])
                 : "r"(a[0]), "r"(a[1]), "r"(a[2]), "r"(a[3]), "r"(b[0]), "r"(b[1]));
}

// ==================== mma.sync fp16 GEMM ====================
// C[M,N] = A[M,K] @ W[N,K]^T. 128 x NT tile, K-tile 64, 3-stage cp.async ring.
// OP 1: softplus+bias -> fp16 | OP 2: transpose+residual fp32 | OP 3: split-K fp32 partials
// OP 4: plain fp16 store
template <int OP, int NT>
__global__ __launch_bounds__(256, 2)
void gemm_mma(const __half* __restrict__ A, int lda,
              const __half* __restrict__ W, int ldw,
              void* __restrict__ Cout, int ldc,
              int M, int N, int Kext,
              const float* __restrict__ bias,
              const float* __restrict__ resid) {
    constexpr int SA     = 128 * 128;
    constexpr int SB     = NT * 128;
    constexpr int STAGE  = SA + SB;
    constexpr int WCOLS  = NT / 2;
    constexpr int NFR    = WCOLS / 8;
    constexpr int BLD    = WCOLS / 16;
    constexpr int BCHUNK = NT * 8 / 256;

    extern __shared__ float4 dyn4[];
    uint32_t base = smem_u32(dyn4);

    int tid = threadIdx.x, lane = tid & 31, warp = tid >> 5;
    int wm = warp & 3, wn = warp >> 2;
    int rowBase = blockIdx.y * 128, colBase = blockIdx.x * NT;

    float* Cf = (float*)Cout;
    __half* Ch = (__half*)Cout;

    int kStart = 0;
    if (OP == 3) {
        int ch = Kext / SPLITK;
        kStart = blockIdx.z * ch;
        Kext = ch;
        Cf += (size_t)blockIdx.z * M * ldc;
    }
    int nTiles = Kext / 64;

    float acc[2][NFR][4];
#pragma unroll
    for (int i = 0; i < 2; i++)
#pragma unroll
        for (int j = 0; j < NFR; j++)
#pragma unroll
            for (int e = 0; e < 4; e++) acc[i][j][e] = 0.f;

    auto load_tile = [&](int s, int kt) {
        uint32_t aB = base + s * STAGE, bB = aB + SA;
        int k0 = kStart + kt * 64;
#pragma unroll
        for (int i = 0; i < 4; i++) {
            int idx = tid + i * 256;
            int row = idx >> 3, c = idx & 7;
            cp16(aB + row * 128 + ((c ^ (row & 7)) << 4),
                 A + (size_t)(rowBase + row) * lda + k0 + c * 8, true);
        }
#pragma unroll
        for (int i = 0; i < BCHUNK; i++) {
            int idx = tid + i * 256;
            int row = idx >> 3, c = idx & 7;
            bool ok = (colBase + row) < N;
            cp16(bB + row * 128 + ((c ^ (row & 7)) << 4),
                 W + (ok ? (size_t)(colBase + row) * ldw : 0) + k0 + c * 8, ok);
        }
        asm volatile("cp.async.commit_group;\n");
    };

    load_tile(0, 0);
    if (nTiles > 1) load_tile(1, 1);

    for (int t = 0; t < nTiles; t++) {
        if (t + 1 >= nTiles) asm volatile("cp.async.wait_group 0;\n");
        else                 asm volatile("cp.async.wait_group 1;\n");
        __syncthreads();

        int s = t % 3;
        uint32_t aB = base + s * STAGE, bB = aB + SA;
#pragma unroll
        for (int ks = 0; ks < 4; ks++) {
            uint32_t afr[2][4];
#pragma unroll
            for (int mt = 0; mt < 2; mt++) {
                int row = wm * 32 + mt * 16 + (lane & 15);
                int unit = ks * 2 + (lane >> 4);
                ldsm4(afr[mt][0], afr[mt][1], afr[mt][2], afr[mt][3],
                      aB + row * 128 + ((unit ^ (row & 7)) << 4));
            }
            uint32_t bfr[NFR][2];
#pragma unroll
            for (int p = 0; p < BLD; p++) {
                int row = wn * WCOLS + p * 16 + (lane & 15);
                int unit = ks * 2 + (lane >> 4);
                uint32_t r0, r1, r2, r3;
                ldsm4(r0, r1, r2, r3, bB + row * 128 + ((unit ^ (row & 7)) << 4));
                bfr[2 * p][0] = r0; bfr[2 * p + 1][0] = r1;
                bfr[2 * p][1] = r2; bfr[2 * p + 1][1] = r3;
            }
#pragma unroll
            for (int mt = 0; mt < 2; mt++)
#pragma unroll
                for (int nt = 0; nt < NFR; nt++)
                    mma16816(acc[mt][nt], afr[mt], bfr[nt]);
        }
        if (t + 2 < nTiles) load_tile((t + 2) % 3, t + 2);
    }

    if (OP == 2) {
        // smem-staged transpose, coalesced fp32 writeback with residual
        __syncthreads();
        float* st = (float*)dyn4;
        const int PITCH = 132;
#pragma unroll
        for (int mt = 0; mt < 2; mt++)
#pragma unroll
            for (int nt = 0; nt < NFR; nt++)
#pragma unroll
                for (int e = 0; e < 4; e++) {
                    int ml = wm * 32 + mt * 16 + (lane >> 2) + ((e >= 2) ? 8 : 0);
                    int nl = wn * WCOLS + nt * 8 + (lane & 3) * 2 + (e & 1);
                    st[nl * PITCH + ml] = acc[mt][nt][e];
                }
        __syncthreads();
        int b = rowBase >> 10, t0 = rowBase & 1023;
        for (int r = warp; r < 128; r += 8) {
            float4 v = *(float4*)&st[r * PITCH + lane * 4];
            size_t oi = (size_t)b * CC * TT + (size_t)(colBase + r) * TT + t0 + lane * 4;
            float4 rv = *(const float4*)(resid + oi);
            v.x += rv.x; v.y += rv.y; v.z += rv.z; v.w += rv.w;
            *(float4*)(Cf + oi) = v;
        }
    } else if (OP == 3) {
#pragma unroll
        for (int mt = 0; mt < 2; mt++) {
            int m = rowBase + wm * 32 + mt * 16 + (lane >> 2);
#pragma unroll
            for (int nt = 0; nt < NFR; nt++) {
                int c0 = colBase + wn * WCOLS + nt * 8 + (lane & 3) * 2;
#pragma unroll
                for (int e = 0; e < 4; e++) {
                    int mm = m + ((e >= 2) ? 8 : 0);
                    int n = c0 + (e & 1);
                    if (n >= N) continue;
                    Cf[(size_t)mm * ldc + n] = acc[mt][nt][e];
                }
            }
        }
    } else {  // OP 1 / OP 4: fp16 half2-packed stores
#pragma unroll
        for (int mt = 0; mt < 2; mt++) {
            int m = rowBase + wm * 32 + mt * 16 + (lane >> 2);
#pragma unroll
            for (int nt = 0; nt < NFR; nt++) {
                int c0 = colBase + wn * WCOLS + nt * 8 + (lane & 3) * 2;
#pragma unroll
                for (int half8 = 0; half8 < 2; half8++) {       // 0: row m, 1: row m+8
                    int mm = m + half8 * 8;
                    float v0 = acc[mt][nt][half8 * 2 + 0];
                    float v1 = acc[mt][nt][half8 * 2 + 1];
                    if (OP == 1) {
                        v0 += bias[c0];     v1 += bias[c0 + 1];
                        v0 = (v0 > 20.f) ? v0 : log1pf(__expf(v0));
                        v1 = (v1 > 20.f) ? v1 : log1pf(__expf(v1));
                    }
                    *(__half2*)(Ch + (size_t)mm * ldc + c0) = __floats2half2_rn(v0, v1);
                }
            }
        }
    }
}

// ==================== LayerNorm: 4 tokens/block, float4 reads along t ====================
__global__ __launch_bounds__(256) void ln_kernel(const float* __restrict__ x,
                                                 const float* __restrict__ w,
                                                 const float* __restrict__ bvec) {
    int blk = blockIdx.x;                 // 512 blocks
    int b  = blk >> 8;
    int t0 = (blk & 255) * 4;
    int c0 = threadIdx.x * 4;

    float va[4][4];                        // [ci][t]
    float s[4] = {0, 0, 0, 0}, s2[4] = {0, 0, 0, 0};
#pragma unroll
    for (int ci = 0; ci < 4; ci++) {
        int c = c0 + ci;
        float4 v = *(const float4*)(x + (size_t)b * CC * TT + (size_t)c * TT + t0);
        va[ci][0] = v.x; va[ci][1] = v.y; va[ci][2] = v.z; va[ci][3] = v.w;
#pragma unroll
        for (int t = 0; t < 4; t++) {
            s[t] += va[ci][t];
            s2[t] = fmaf(va[ci][t], va[ci][t], s2[t]);
        }
    }
#pragma unroll
    for (int o = 16; o; o >>= 1)
#pragma unroll
        for (int t = 0; t < 4; t++) {
            s[t]  += __shfl_xor_sync(0xffffffffu, s[t],  o);
            s2[t] += __shfl_xor_sync(0xffffffffu, s2[t], o);
        }
    __shared__ float sh[8][8];             // [q][warp]
    int wp = threadIdx.x >> 5, ln = threadIdx.x & 31;
    if (ln == 0) {
#pragma unroll
        for (int t = 0; t < 4; t++) { sh[t][wp] = s[t]; sh[4 + t][wp] = s2[t]; }
    }
    __syncthreads();
    float mu[4], rs[4];
#pragma unroll
    for (int t = 0; t < 4; t++) {
        float S = 0.f, S2 = 0.f;
#pragma unroll
        for (int i = 0; i < 8; i++) { S += sh[t][i]; S2 += sh[4 + t][i]; }
        mu[t] = S * (1.f / 1024.f);
        float var = S2 * (1.f / 1024.f) - mu[t] * mu[t];
        rs[t] = rsqrtf(var + 1e-5f);
    }
    float wv[4], bv[4];
#pragma unroll
    for (int ci = 0; ci < 4; ci++) { wv[ci] = w[c0 + ci]; bv[ci] = bvec[c0 + ci]; }
#pragma unroll
    for (int t = 0; t < 4; t++) {
        int tok = b * TT + t0 + t;
        float o0 = (va[0][t] - mu[t]) * rs[t] * wv[0] + bv[0];
        float o1 = (va[1][t] - mu[t]) * rs[t] * wv[1] + bv[1];
        float o2 = (va[2][t] - mu[t]) * rs[t] * wv[2] + bv[2];
        float o3 = (va[3][t] - mu[t]) * rs[t] * wv[3] + bv[3];
        __half2* op = (__half2*)(e_xn + (size_t)tok * CC + c0);
        op[0] = __floats2half2_rn(o0, o1);
        op[1] = __floats2half2_rn(o2, o3);
    }
}

// single-launch fp32->fp16 cast over 4 weight segments
struct Cvt4 {
    const float* in0; const float* in1; const float* in2; const float* in3;
    __half* out0; __half* out1; __half* out2; __half* out3;
    int c0, c1, c2, c3;
};
__global__ __launch_bounds__(256) void convert4_kernel(Cvt4 c) {
    int i = blockIdx.x * 256 + threadIdx.x;
    if (i >= c.c3) return;
    const float* in; __half* out; int j;
    if (i < c.c0)      { in = c.in0; out = c.out0; j = i; }
    else if (i < c.c1) { in = c.in1; out = c.out1; j = i - c.c0; }
    else if (i < c.c2) { in = c.in2; out = c.out2; j = i - c.c1; }
    else               { in = c.in3; out = c.out3; j = i - c.c2; }
    float2 v = *(const float2*)(in + (size_t)j * 2);
    *(__half2*)(out + (size_t)j * 2) = __floats2half2_rn(v.x, v.y);
}

// split-K reduce + fused dt_raw fp16 conversion
__global__ __launch_bounds__(256) void reduce_part_kernel() {
    int i = blockIdx.x * 256 + threadIdx.x;
    if (i >= TOKS * XDBL) return;
    float s = 0.f;
#pragma unroll
    for (int z = 0; z < SPLITK; z++) s += g_part[(size_t)z * TOKS * XDBL + i];
    g_xdbl[i] = s;
    int tok = i / XDBL, k = i - tok * XDBL;
    if (k < DTRANK) e_dtr[(size_t)tok * DTRANK + k] = __float2half_rn(s);
}

// conv+SiLU: fp16 in (e_xz), fp16 out (e_xc); 4 consecutive t per thread
__global__ __launch_bounds__(256) void conv_silu_kernel(const float* __restrict__ conv_w,
                                                        const float* __restrict__ conv_b) {
    int i = blockIdx.x * 256 + threadIdx.x;
    int d = i & (DIN - 1);
    int tg = i >> 11;
    int b = tg >> 8;
    int t0 = (tg & 255) * 4;

    float w0 = conv_w[d * DCONV + 0];
    float w1 = conv_w[d * DCONV + 1];
    float w2 = conv_w[d * DCONV + 2];
    float w3 = conv_w[d * DCONV + 3];
    float bias = conv_b[d];

    const __half* xin = e_xz + (size_t)(b * TT) * (2 * DIN) + d;
    float xv[7];
#pragma unroll
    for (int j = 0; j < 7; j++) {
        int t = t0 - 3 + j;
        xv[j] = (t >= 0) ? __half2float(xin[(size_t)t * (2 * DIN)]) : 0.f;
    }
#pragma unroll
    for (int k = 0; k < 4; k++) {
        float v = bias;
        v = fmaf(w0, xv[k],     v);
        v = fmaf(w1, xv[k + 1], v);
        v = fmaf(w2, xv[k + 2], v);
        v = fmaf(w3, xv[k + 3], v);
        float sig = 1.f / (1.f + __expf(-v));
        e_xc[(size_t)(b * TT + t0 + k) * DIN + d] = __float2half_rn(v * sig);
    }
}

// ==================== windowed smem selective scan (fp16 panels) ====================
__global__ __launch_bounds__(512) void scan_kernel(const float* __restrict__ A_log,
                                                   const float* __restrict__ Dvec) {
    __shared__ __align__(16) __half s_h[2][3][SW * 32];   // dt, xc, z
    __shared__ __align__(16) float  s_bc[2][SW * 32];     // B|C fp32
    __shared__ float s_y[SW][32];

    int tid  = threadIdx.x;
    int lane = tid & 31, warp = tid >> 5;
    int chBase = blockIdx.x * 32;
    int b  = chBase >> 11;
    int d0 = chBase & (DIN - 1);
    int s  = lane & 15;
    int dloc = warp * 2 + (lane >> 4);
    int d = d0 + dloc;

    float A_s = -__expf(A_log[d * DSTATE + s]);
    float Dd  = Dvec[d];

    const __half* dtH = e_dt + (size_t)(b * TT) * DIN + d0;
    const __half* xcH = e_xc + (size_t)(b * TT) * DIN + d0;
    const __half* zH  = e_xz + (size_t)(b * TT) * (2 * DIN) + DIN + d0;
    const float*  bcG = g_xdbl + (size_t)(b * TT) * XDBL + DTRANK;

    auto load_win = [&](int w, int buf) {
        int t0 = w * SW;
        // 1280 16B chunks: 3 half arrays x 256 + bc 512
        for (int i = tid; i < 1280; i += 512) {
            uint32_t dst; const void* src;
            if (i < 768) {
                int a = i >> 8, r = i & 255;
                int t = r >> 2, seg = r & 3;
                dst = smem_u32(&s_h[buf][a][t * 32 + seg * 8]);
                const __half* bp = (a == 0) ? dtH : (a == 1) ? xcH : zH;
                size_t stride = (a == 2) ? (size_t)(2 * DIN) : (size_t)DIN;
                src = bp + (size_t)(t0 + t) * stride + seg * 8;
            } else {
                int r = i - 768;
                int t = r >> 3, seg = r & 7;
                dst = smem_u32(&s_bc[buf][t * 32 + seg * 4]);
                src = bcG + (size_t)(t0 + t) * XDBL + seg * 4;
            }
            cp16(dst, src, true);
        }
        asm volatile("cp.async.commit_group;\n");
    };

    constexpr int NW = TT / SW;
    load_win(0, 0);
    int buf = 0;
    float h = 0.f;

    for (int w = 0; w < NW; w++) {
        if (w + 1 < NW) {
            load_win(w + 1, buf ^ 1);
            asm volatile("cp.async.wait_group 1;\n");
        } else {
            asm volatile("cp.async.wait_group 0;\n");
        }
        __syncthreads();

        const __half* fDT = s_h[buf][0];
        const __half* fXC = s_h[buf][1];
        const float*  fBC = s_bc[buf];
#pragma unroll 4
        for (int t = 0; t < SW; t++) {
            float dtv = __half2float(fDT[t * 32 + dloc]);
            float xv  = __half2float(fXC[t * 32 + dloc]);
            float Bv  = fBC[t * 32 + s];
            float Cv  = fBC[t * 32 + 16 + s];
            float dA  = __expf(dtv * A_s);
            h = fmaf(dA, h, dtv * Bv * xv);
            float p = h * Cv;
            p += __shfl_xor_sync(0xffffffffu, p, 8);
            p += __shfl_xor_sync(0xffffffffu, p, 4);
            p += __shfl_xor_sync(0xffffffffu, p, 2);
            p += __shfl_xor_sync(0xffffffffu, p, 1);
            if (s == 0) s_y[t][dloc] = fmaf(Dd, xv, p);
        }
        __syncthreads();

        const __half* fZ = s_h[buf][2];
        int t0 = w * SW;
#pragma unroll
        for (int k = 0; k < 4; k++) {
            int idx = tid + k * 512;
            int t = idx >> 5, dd = idx & 31;
            float yv = s_y[t][dd];
            float zv = __half2float(fZ[t * 32 + dd]);
            float sig = 1.f / (1.f + __expf(-zv));
            yv *= zv * sig;
            e_y[(size_t)(b * TT + t0 + t) * DIN + d0 + dd] = __float2half_rn(yv);
        }
        __syncthreads();
        buf ^= 1;
    }
}

// ==================== launch ====================
extern "C" void kernel_launch(void* const* d_in, const int* in_sizes, int n_in,
                              void* d_out, int out_size) {
    const float* x          = (const float*)d_in[0];
    const float* norm_w     = (const float*)d_in[1];
    const float* norm_b     = (const float*)d_in[2];
    const float* in_proj_w  = (const float*)d_in[3];
    const float* conv_w     = (const float*)d_in[4];
    const float* conv_b     = (const float*)d_in[5];
    const float* x_proj_w   = (const float*)d_in[6];
    const float* dt_proj_w  = (const float*)d_in[7];
    const float* dt_proj_b  = (const float*)d_in[8];
    const float* A_log      = (const float*)d_in[9];
    const float* Dvec       = (const float*)d_in[10];
    const float* out_proj_w = (const float*)d_in[11];
    float* out = (float*)d_out;

    float *part;
    __half *exn, *ew1, *exz, *exc, *ew2, *edtr, *ew3, *edt, *ey, *ew4;
    cudaGetSymbolAddress((void**)&part, g_part);
    cudaGetSymbolAddress((void**)&exn,  e_xn);
    cudaGetSymbolAddress((void**)&ew1,  e_w1);
    cudaGetSymbolAddress((void**)&exz,  e_xz);
    cudaGetSymbolAddress((void**)&exc,  e_xc);
    cudaGetSymbolAddress((void**)&ew2,  e_w2);
    cudaGetSymbolAddress((void**)&edtr, e_dtr);
    cudaGetSymbolAddress((void**)&ew3,  e_w3);
    cudaGetSymbolAddress((void**)&edt,  e_dt);
    cudaGetSymbolAddress((void**)&ey,   e_y);
    cudaGetSymbolAddress((void**)&ew4,  e_w4);

    const int smem128 = 3 * (128 * 128 + 128 * 128);   // 98304
    cudaFuncSetAttribute(gemm_mma<4, 128>, cudaFuncAttributeMaxDynamicSharedMemorySize, smem128);
    cudaFuncSetAttribute(gemm_mma<1, 128>, cudaFuncAttributeMaxDynamicSharedMemorySize, smem128);
    cudaFuncSetAttribute(gemm_mma<3, 128>, cudaFuncAttributeMaxDynamicSharedMemorySize, smem128);
    cudaFuncSetAttribute(gemm_mma<2, 128>, cudaFuncAttributeMaxDynamicSharedMemorySize, smem128);

    // 1. all weight converts in one launch
    Cvt4 cv;
    cv.in0 = in_proj_w;  cv.out0 = ew1;
    cv.in1 = out_proj_w; cv.out1 = ew4;
    cv.in2 = x_proj_w;   cv.out2 = ew2;
    cv.in3 = dt_proj_w;  cv.out3 = ew3;
    int n0 = 2 * DIN * CC / 2, n1 = CC * DIN / 2, n2 = XDBL * DIN / 2, n3 = DIN * DTRANK / 2;
    cv.c0 = n0; cv.c1 = n0 + n1; cv.c2 = n0 + n1 + n2; cv.c3 = n0 + n1 + n2 + n3;
    convert4_kernel<<<(cv.c3 + 255) / 256, 256>>>(cv);
    // 2. LayerNorm (4 tok/block)
    ln_kernel<<<TOKS / 4, 256>>>(x, norm_w, norm_b);
    // 3. in_proj GEMM -> e_xz fp16
    gemm_mma<4, 128><<<dim3((2 * DIN) / 128, TOKS / 128), 256, smem128>>>(
        exn, CC, ew1, CC, exz, 2 * DIN, TOKS, 2 * DIN, CC, nullptr, nullptr);
    // 4. conv + SiLU (PROFILED LAUNCH)
    conv_silu_kernel<<<(TOKS / 4) * DIN / 256, 256>>>(conv_w, conv_b);
    // 5. x_proj split-K GEMM
    gemm_mma<3, 128><<<dim3(1, TOKS / 128, SPLITK), 256, smem128>>>(
        exc, DIN, ew2, DIN, part, XDBL, TOKS, XDBL, DIN, nullptr, nullptr);
    // 6. reduce partials + dt_raw fp16
    reduce_part_kernel<<<(TOKS * XDBL + 255) / 256, 256>>>();
    // 7. dt_proj + softplus -> e_dt fp16
    gemm_mma<1, 128><<<dim3(DIN / 128, TOKS / 128), 256, smem128>>>(
        edtr, DTRANK, ew3, DTRANK, edt, DIN, TOKS, DIN, DTRANK, dt_proj_b, nullptr);
    // 8. selective scan + gate
    scan_kernel<<<(BB * DIN) / 32, 512>>>(A_log, Dvec);
    // 9. out_proj + residual, transposed store
    gemm_mma<2, 128><<<dim3(CC / 128, TOKS / 128), 256, smem128>>>(
        ey, DIN, ew4, DIN, out, 0, TOKS, CC, DIN, nullptr, x);
}

// round 12
// speedup vs baseline: 1.5228x; 1.0210x over previous
#include <cuda_runtime.h>
#include <cuda_fp16.h>
#include <math.h>
#include <stdint.h>

// ---------------- problem constants ----------------
#define BB      2
#define CC      1024
#define TT      1024
#define TOKS    (BB * TT)          // 2048
#define DIN     2048
#define DSTATE  16
#define DTRANK  64
#define XDBL    96
#define DCONV   4
#define SPLITK  8
#define SW      64                 // scan window (t-steps)

// ---------------- fp32 scratch ----------------
__device__ float g_xdbl[TOKS * XDBL];
__device__ float g_part[SPLITK * TOKS * XDBL];

// ---------------- fp16 scratch ----------------
__device__ __half e_xn [TOKS * CC];
__device__ __half e_w1 [2 * DIN * CC];
__device__ __half e_xz [TOKS * 2 * DIN];
__device__ __half e_xc [TOKS * DIN];
__device__ __half e_w2 [XDBL * DIN];
__device__ __half e_dtr[TOKS * DTRANK];
__device__ __half e_w3 [DIN * DTRANK];
__device__ __half e_dt [TOKS * DIN];
__device__ __half e_y  [TOKS * DIN];
__device__ __half e_w4 [CC * DIN];

// ==================== PTX helpers ====================
__device__ __forceinline__ uint32_t smem_u32(const void* p) {
    uint32_t a;
    asm("{ .reg .u64 t; cvta.to.shared.u64 t, %1; cvt.u32.u64 %0, t; }" : "=r"(a) : "l"(p));
    return a;
}
__device__ __forceinline__ void cp16(uint32_t dst, const void* src, bool pred) {
    int sz = pred ? 16 : 0;
    asm volatile("cp.async.cg.shared.global [%0], [%1], 16, %2;\n" :: "r"(dst), "l"(src), "r"(sz));
}
__device__ __forceinline__ void ldsm4(uint32_t& r0, uint32_t& r1, uint32_t& r2, uint32_t& r3,
                                      uint32_t addr) {
    asm volatile("ldmatrix.sync.aligned.m8n8.x4.shared.b16 {%0,%1,%2,%3}, [%4];"
                 : "=r"(r0), "=r"(r1), "=r"(r2), "=r"(r3) : "r"(addr));
}
__device__ __forceinline__ void mma16816(float* c, const uint32_t* a, const uint32_t* b) {
    asm volatile("mma.sync.aligned.m16n8k16.row.col.f32.f16.f16.f32 "
                 "{%0,%1,%2,%3}, {%4,%5,%6,%7}, {%8,%9}, {%0,%1,%2,%3};"
                 : "+f"(c[0]), "+f"(c[1]), "+f"(c[2]), "+f"(c[3])
                 : "r"(a[0]), "r"(a[1]), "r"(a[2]), "r"(a[3]), "r"(b[0]), "r"(b[1]));
}

// ==================== mma.sync fp16 GEMM ====================
// OP 1: softplus+bias -> fp16 | OP 2: transpose+residual fp32 | OP 3: split-K fp32 partials
// OP 4: plain fp16 store
template <int OP, int NT>
__global__ __launch_bounds__(256, 2)
void gemm_mma(const __half* __restrict__ A, int lda,
              const __half* __restrict__ W, int ldw,
              void* __restrict__ Cout, int ldc,
              int M, int N, int Kext,
              const float* __restrict__ bias,
              const float* __restrict__ resid) {
    constexpr int SA     = 128 * 128;
    constexpr int SB     = NT * 128;
    constexpr int STAGE  = SA + SB;
    constexpr int WCOLS  = NT / 2;
    constexpr int NFR    = WCOLS / 8;
    constexpr int BLD    = WCOLS / 16;
    constexpr int BCHUNK = NT * 8 / 256;

    extern __shared__ float4 dyn4[];
    uint32_t base = smem_u32(dyn4);

    int tid = threadIdx.x, lane = tid & 31, warp = tid >> 5;
    int wm = warp & 3, wn = warp >> 2;
    int rowBase = blockIdx.y * 128, colBase = blockIdx.x * NT;

    float* Cf = (float*)Cout;
    __half* Ch = (__half*)Cout;

    int kStart = 0;
    if (OP == 3) {
        int ch = Kext / SPLITK;
        kStart = blockIdx.z * ch;
        Kext = ch;
        Cf += (size_t)blockIdx.z * M * ldc;
    }
    int nTiles = Kext / 64;

    float acc[2][NFR][4];
#pragma unroll
    for (int i = 0; i < 2; i++)
#pragma unroll
        for (int j = 0; j < NFR; j++)
#pragma unroll
            for (int e = 0; e < 4; e++) acc[i][j][e] = 0.f;

    auto load_tile = [&](int s, int kt) {
        uint32_t aB = base + s * STAGE, bB = aB + SA;
        int k0 = kStart + kt * 64;
#pragma unroll
        for (int i = 0; i < 4; i++) {
            int idx = tid + i * 256;
            int row = idx >> 3, c = idx & 7;
            cp16(aB + row * 128 + ((c ^ (row & 7)) << 4),
                 A + (size_t)(rowBase + row) * lda + k0 + c * 8, true);
        }
#pragma unroll
        for (int i = 0; i < BCHUNK; i++) {
            int idx = tid + i * 256;
            int row = idx >> 3, c = idx & 7;
            bool ok = (colBase + row) < N;
            cp16(bB + row * 128 + ((c ^ (row & 7)) << 4),
                 W + (ok ? (size_t)(colBase + row) * ldw : 0) + k0 + c * 8, ok);
        }
        asm volatile("cp.async.commit_group;\n");
    };

    load_tile(0, 0);
    if (nTiles > 1) load_tile(1, 1);

    for (int t = 0; t < nTiles; t++) {
        if (t + 1 >= nTiles) asm volatile("cp.async.wait_group 0;\n");
        else                 asm volatile("cp.async.wait_group 1;\n");
        __syncthreads();

        int s = t % 3;
        uint32_t aB = base + s * STAGE, bB = aB + SA;
#pragma unroll
        for (int ks = 0; ks < 4; ks++) {
            uint32_t afr[2][4];
#pragma unroll
            for (int mt = 0; mt < 2; mt++) {
                int row = wm * 32 + mt * 16 + (lane & 15);
                int unit = ks * 2 + (lane >> 4);
                ldsm4(afr[mt][0], afr[mt][1], afr[mt][2], afr[mt][3],
                      aB + row * 128 + ((unit ^ (row & 7)) << 4));
            }
            uint32_t bfr[NFR][2];
#pragma unroll
            for (int p = 0; p < BLD; p++) {
                int row = wn * WCOLS + p * 16 + (lane & 15);
                int unit = ks * 2 + (lane >> 4);
                uint32_t r0, r1, r2, r3;
                ldsm4(r0, r1, r2, r3, bB + row * 128 + ((unit ^ (row & 7)) << 4));
                bfr[2 * p][0] = r0; bfr[2 * p + 1][0] = r1;
                bfr[2 * p][1] = r2; bfr[2 * p + 1][1] = r3;
            }
#pragma unroll
            for (int mt = 0; mt < 2; mt++)
#pragma unroll
                for (int nt = 0; nt < NFR; nt++)
                    mma16816(acc[mt][nt], afr[mt], bfr[nt]);
        }
        if (t + 2 < nTiles) load_tile((t + 2) % 3, t + 2);
    }

    if (OP == 2) {
        __syncthreads();
        float* st = (float*)dyn4;
        const int PITCH = 132;
#pragma unroll
        for (int mt = 0; mt < 2; mt++)
#pragma unroll
            for (int nt = 0; nt < NFR; nt++)
#pragma unroll
                for (int e = 0; e < 4; e++) {
                    int ml = wm * 32 + mt * 16 + (lane >> 2) + ((e >= 2) ? 8 : 0);
                    int nl = wn * WCOLS + nt * 8 + (lane & 3) * 2 + (e & 1);
                    st[nl * PITCH + ml] = acc[mt][nt][e];
                }
        __syncthreads();
        int b = rowBase >> 10, t0 = rowBase & 1023;
        for (int r = warp; r < 128; r += 8) {
            float4 v = *(float4*)&st[r * PITCH + lane * 4];
            size_t oi = (size_t)b * CC * TT + (size_t)(colBase + r) * TT + t0 + lane * 4;
            float4 rv = *(const float4*)(resid + oi);
            v.x += rv.x; v.y += rv.y; v.z += rv.z; v.w += rv.w;
            *(float4*)(Cf + oi) = v;
        }
    } else if (OP == 3) {
#pragma unroll
        for (int mt = 0; mt < 2; mt++) {
            int m = rowBase + wm * 32 + mt * 16 + (lane >> 2);
#pragma unroll
            for (int nt = 0; nt < NFR; nt++) {
                int c0 = colBase + wn * WCOLS + nt * 8 + (lane & 3) * 2;
#pragma unroll
                for (int e = 0; e < 4; e++) {
                    int mm = m + ((e >= 2) ? 8 : 0);
                    int n = c0 + (e & 1);
                    if (n >= N) continue;
                    Cf[(size_t)mm * ldc + n] = acc[mt][nt][e];
                }
            }
        }
    } else {  // OP 1 / OP 4
#pragma unroll
        for (int mt = 0; mt < 2; mt++) {
            int m = rowBase + wm * 32 + mt * 16 + (lane >> 2);
#pragma unroll
            for (int nt = 0; nt < NFR; nt++) {
                int c0 = colBase + wn * WCOLS + nt * 8 + (lane & 3) * 2;
#pragma unroll
                for (int half8 = 0; half8 < 2; half8++) {
                    int mm = m + half8 * 8;
                    float v0 = acc[mt][nt][half8 * 2 + 0];
                    float v1 = acc[mt][nt][half8 * 2 + 1];
                    if (OP == 1) {
                        v0 += bias[c0];     v1 += bias[c0 + 1];
                        v0 = (v0 > 20.f) ? v0 : log1pf(__expf(v0));
                        v1 = (v1 > 20.f) ? v1 : log1pf(__expf(v1));
                    }
                    *(__half2*)(Ch + (size_t)mm * ldc + c0) = __floats2half2_rn(v0, v1);
                }
            }
        }
    }
}

// ==================== fused weight-convert + LayerNorm (single launch) ====================
struct Cvt4 {
    const float* in0; const float* in1; const float* in2; const float* in3;
    __half* out0; __half* out1; __half* out2; __half* out3;
    int c0, c1, c2, c3;
};
#define LN_BLOCKS (TOKS / 4)
__global__ __launch_bounds__(256) void cvt_ln_kernel(Cvt4 c,
                                                     const float* __restrict__ x,
                                                     const float* __restrict__ w,
                                                     const float* __restrict__ bvec) {
    if (blockIdx.x >= LN_BLOCKS) {
        // ---- weight convert part ----
        int i = (blockIdx.x - LN_BLOCKS) * 256 + threadIdx.x;
        if (i >= c.c3) return;
        const float* in; __half* out; int j;
        if (i < c.c0)      { in = c.in0; out = c.out0; j = i; }
        else if (i < c.c1) { in = c.in1; out = c.out1; j = i - c.c0; }
        else if (i < c.c2) { in = c.in2; out = c.out2; j = i - c.c1; }
        else               { in = c.in3; out = c.out3; j = i - c.c2; }
        float2 v = *(const float2*)(in + (size_t)j * 2);
        *(__half2*)(out + (size_t)j * 2) = __floats2half2_rn(v.x, v.y);
        return;
    }
    // ---- LayerNorm part: 4 tokens/block ----
    int blk = blockIdx.x;
    int b  = blk >> 8;
    int t0 = (blk & 255) * 4;
    int c0 = threadIdx.x * 4;

    float va[4][4];
    float s[4] = {0, 0, 0, 0}, s2[4] = {0, 0, 0, 0};
#pragma unroll
    for (int ci = 0; ci < 4; ci++) {
        float4 v = *(const float4*)(x + (size_t)b * CC * TT + (size_t)(c0 + ci) * TT + t0);
        va[ci][0] = v.x; va[ci][1] = v.y; va[ci][2] = v.z; va[ci][3] = v.w;
#pragma unroll
        for (int t = 0; t < 4; t++) {
            s[t] += va[ci][t];
            s2[t] = fmaf(va[ci][t], va[ci][t], s2[t]);
        }
    }
#pragma unroll
    for (int o = 16; o; o >>= 1)
#pragma unroll
        for (int t = 0; t < 4; t++) {
            s[t]  += __shfl_xor_sync(0xffffffffu, s[t],  o);
            s2[t] += __shfl_xor_sync(0xffffffffu, s2[t], o);
        }
    __shared__ float sh[8][8];
    int wp = threadIdx.x >> 5, ln = threadIdx.x & 31;
    if (ln == 0) {
#pragma unroll
        for (int t = 0; t < 4; t++) { sh[t][wp] = s[t]; sh[4 + t][wp] = s2[t]; }
    }
    __syncthreads();
    float mu[4], rs[4];
#pragma unroll
    for (int t = 0; t < 4; t++) {
        float S = 0.f, S2 = 0.f;
#pragma unroll
        for (int i = 0; i < 8; i++) { S += sh[t][i]; S2 += sh[4 + t][i]; }
        mu[t] = S * (1.f / 1024.f);
        float var = S2 * (1.f / 1024.f) - mu[t] * mu[t];
        rs[t] = rsqrtf(var + 1e-5f);
    }
    float wv[4], bv[4];
#pragma unroll
    for (int ci = 0; ci < 4; ci++) { wv[ci] = w[c0 + ci]; bv[ci] = bvec[c0 + ci]; }
#pragma unroll
    for (int t = 0; t < 4; t++) {
        int tok = b * TT + t0 + t;
        float o0 = (va[0][t] - mu[t]) * rs[t] * wv[0] + bv[0];
        float o1 = (va[1][t] - mu[t]) * rs[t] * wv[1] + bv[1];
        float o2 = (va[2][t] - mu[t]) * rs[t] * wv[2] + bv[2];
        float o3 = (va[3][t] - mu[t]) * rs[t] * wv[3] + bv[3];
        __half2* op = (__half2*)(e_xn + (size_t)tok * CC + c0);
        op[0] = __floats2half2_rn(o0, o1);
        op[1] = __floats2half2_rn(o2, o3);
    }
}

// split-K reduce + fused dt_raw fp16 conversion
__global__ __launch_bounds__(256) void reduce_part_kernel() {
    int i = blockIdx.x * 256 + threadIdx.x;
    if (i >= TOKS * XDBL) return;
    float s = 0.f;
#pragma unroll
    for (int z = 0; z < SPLITK; z++) s += g_part[(size_t)z * TOKS * XDBL + i];
    g_xdbl[i] = s;
    int tok = i / XDBL, k = i - tok * XDBL;
    if (k < DTRANK) e_dtr[(size_t)tok * DTRANK + k] = __float2half_rn(s);
}

// conv+SiLU: fp16 in/out; 4 consecutive t per thread
__global__ __launch_bounds__(256) void conv_silu_kernel(const float* __restrict__ conv_w,
                                                        const float* __restrict__ conv_b) {
    int i = blockIdx.x * 256 + threadIdx.x;
    int d = i & (DIN - 1);
    int tg = i >> 11;
    int b = tg >> 8;
    int t0 = (tg & 255) * 4;

    float w0 = conv_w[d * DCONV + 0];
    float w1 = conv_w[d * DCONV + 1];
    float w2 = conv_w[d * DCONV + 2];
    float w3 = conv_w[d * DCONV + 3];
    float bias = conv_b[d];

    const __half* xin = e_xz + (size_t)(b * TT) * (2 * DIN) + d;
    float xv[7];
#pragma unroll
    for (int j = 0; j < 7; j++) {
        int t = t0 - 3 + j;
        xv[j] = (t >= 0) ? __half2float(xin[(size_t)t * (2 * DIN)]) : 0.f;
    }
#pragma unroll
    for (int k = 0; k < 4; k++) {
        float v = bias;
        v = fmaf(w0, xv[k],     v);
        v = fmaf(w1, xv[k + 1], v);
        v = fmaf(w2, xv[k + 2], v);
        v = fmaf(w3, xv[k + 3], v);
        float sig = 1.f / (1.f + __expf(-v));
        e_xc[(size_t)(b * TT + t0 + k) * DIN + d] = __float2half_rn(v * sig);
    }
}

// ==================== scan v3: 4 channels x 8 states per warp, 256 threads ====================
__global__ __launch_bounds__(256) void scan_kernel(const float* __restrict__ A_log,
                                                   const float* __restrict__ Dvec) {
    __shared__ __align__(16) __half s_h[2][3][SW * 32];   // dt, xc, z
    __shared__ __align__(16) float  s_bc[2][SW * 32];     // B|C fp32
    __shared__ float s_y[SW][32];

    int tid  = threadIdx.x;
    int lane = tid & 31, warp = tid >> 5;                 // 8 warps
    int chBase = blockIdx.x * 32;
    int b  = chBase >> 11;
    int d0 = chBase & (DIN - 1);
    int cloc = lane >> 3;          // 0..3
    int s    = lane & 7;           // states s and s+8
    int dloc = warp * 4 + cloc;
    int d = d0 + dloc;

    float A1 = -__expf(A_log[d * DSTATE + s]);
    float A2 = -__expf(A_log[d * DSTATE + s + 8]);
    float Dd = Dvec[d];

    const __half* dtH = e_dt + (size_t)(b * TT) * DIN + d0;
    const __half* xcH = e_xc + (size_t)(b * TT) * DIN + d0;
    const __half* zH  = e_xz + (size_t)(b * TT) * (2 * DIN) + DIN + d0;
    const float*  bcG = g_xdbl + (size_t)(b * TT) * XDBL + DTRANK;

    auto load_win = [&](int w, int buf) {
        int t0 = w * SW;
        for (int i = tid; i < 1280; i += 256) {
            uint32_t dst; const void* src;
            if (i < 768) {
                int a = i >> 8, r = i & 255;
                int t = r >> 2, seg = r & 3;
                dst = smem_u32(&s_h[buf][a][t * 32 + seg * 8]);
                const __half* bp = (a == 0) ? dtH : (a == 1) ? xcH : zH;
                size_t stride = (a == 2) ? (size_t)(2 * DIN) : (size_t)DIN;
                src = bp + (size_t)(t0 + t) * stride + seg * 8;
            } else {
                int r = i - 768;
                int t = r >> 3, seg = r & 7;
                dst = smem_u32(&s_bc[buf][t * 32 + seg * 4]);
                src = bcG + (size_t)(t0 + t) * XDBL + seg * 4;
            }
            cp16(dst, src, true);
        }
        asm volatile("cp.async.commit_group;\n");
    };

    constexpr int NW = TT / SW;
    load_win(0, 0);
    int buf = 0;
    float h1 = 0.f, h2 = 0.f;

    for (int w = 0; w < NW; w++) {
        if (w + 1 < NW) {
            load_win(w + 1, buf ^ 1);
            asm volatile("cp.async.wait_group 1;\n");
        } else {
            asm volatile("cp.async.wait_group 0;\n");
        }
        __syncthreads();

        const __half* fDT = s_h[buf][0];
        const __half* fXC = s_h[buf][1];
        const float*  fBC = s_bc[buf];
#pragma unroll 4
        for (int t = 0; t < SW; t++) {
            float dtv = __half2float(fDT[t * 32 + dloc]);
            float xv  = __half2float(fXC[t * 32 + dloc]);
            float B1  = fBC[t * 32 + s];
            float B2  = fBC[t * 32 + 8 + s];
            float C1  = fBC[t * 32 + 16 + s];
            float C2  = fBC[t * 32 + 24 + s];
            float dA1 = __expf(dtv * A1);
            float dA2 = __expf(dtv * A2);
            float dbx = dtv * xv;
            h1 = fmaf(dA1, h1, dbx * B1);
            h2 = fmaf(dA2, h2, dbx * B2);
            float p = fmaf(h2, C2, h1 * C1);
            p += __shfl_xor_sync(0xffffffffu, p, 4);
            p += __shfl_xor_sync(0xffffffffu, p, 2);
            p += __shfl_xor_sync(0xffffffffu, p, 1);
            if (s == 0) s_y[t][dloc] = fmaf(Dd, xv, p);
        }
        __syncthreads();

        const __half* fZ = s_h[buf][2];
        int t0 = w * SW;
#pragma unroll
        for (int k = 0; k < 8; k++) {
            int idx = tid + k * 256;
            int t = idx >> 5, dd = idx & 31;
            float yv = s_y[t][dd];
            float zv = __half2float(fZ[t * 32 + dd]);
            float sig = 1.f / (1.f + __expf(-zv));
            yv *= zv * sig;
            e_y[(size_t)(b * TT + t0 + t) * DIN + d0 + dd] = __float2half_rn(yv);
        }
        __syncthreads();
        buf ^= 1;
    }
}

// ==================== launch ====================
extern "C" void kernel_launch(void* const* d_in, const int* in_sizes, int n_in,
                              void* d_out, int out_size) {
    const float* x          = (const float*)d_in[0];
    const float* norm_w     = (const float*)d_in[1];
    const float* norm_b     = (const float*)d_in[2];
    const float* in_proj_w  = (const float*)d_in[3];
    const float* conv_w     = (const float*)d_in[4];
    const float* conv_b     = (const float*)d_in[5];
    const float* x_proj_w   = (const float*)d_in[6];
    const float* dt_proj_w  = (const float*)d_in[7];
    const float* dt_proj_b  = (const float*)d_in[8];
    const float* A_log      = (const float*)d_in[9];
    const float* Dvec       = (const float*)d_in[10];
    const float* out_proj_w = (const float*)d_in[11];
    float* out = (float*)d_out;

    float *part;
    __half *exn, *ew1, *exz, *exc, *ew2, *edtr, *ew3, *edt, *ey, *ew4;
    cudaGetSymbolAddress((void**)&part, g_part);
    cudaGetSymbolAddress((void**)&exn,  e_xn);
    cudaGetSymbolAddress((void**)&ew1,  e_w1);
    cudaGetSymbolAddress((void**)&exz,  e_xz);
    cudaGetSymbolAddress((void**)&exc,  e_xc);
    cudaGetSymbolAddress((void**)&ew2,  e_w2);
    cudaGetSymbolAddress((void**)&edtr, e_dtr);
    cudaGetSymbolAddress((void**)&ew3,  e_w3);
    cudaGetSymbolAddress((void**)&edt,  e_dt);
    cudaGetSymbolAddress((void**)&ey,   e_y);
    cudaGetSymbolAddress((void**)&ew4,  e_w4);

    const int smem128 = 3 * (128 * 128 + 128 * 128);   // 98304
    cudaFuncSetAttribute(gemm_mma<4, 128>, cudaFuncAttributeMaxDynamicSharedMemorySize, smem128);
    cudaFuncSetAttribute(gemm_mma<1, 128>, cudaFuncAttributeMaxDynamicSharedMemorySize, smem128);
    cudaFuncSetAttribute(gemm_mma<3, 128>, cudaFuncAttributeMaxDynamicSharedMemorySize, smem128);
    cudaFuncSetAttribute(gemm_mma<2, 128>, cudaFuncAttributeMaxDynamicSharedMemorySize, smem128);

    // 1. fused weight converts + LayerNorm
    Cvt4 cv;
    cv.in0 = in_proj_w;  cv.out0 = ew1;
    cv.in1 = out_proj_w; cv.out1 = ew4;
    cv.in2 = x_proj_w;   cv.out2 = ew2;
    cv.in3 = dt_proj_w;  cv.out3 = ew3;
    int n0 = 2 * DIN * CC / 2, n1 = CC * DIN / 2, n2 = XDBL * DIN / 2, n3 = DIN * DTRANK / 2;
    cv.c0 = n0; cv.c1 = n0 + n1; cv.c2 = n0 + n1 + n2; cv.c3 = n0 + n1 + n2 + n3;
    int cvtBlocks = (cv.c3 + 255) / 256;
    cvt_ln_kernel<<<LN_BLOCKS + cvtBlocks, 256>>>(cv, x, norm_w, norm_b);
    // 2. in_proj GEMM -> e_xz fp16
    gemm_mma<4, 128><<<dim3((2 * DIN) / 128, TOKS / 128), 256, smem128>>>(
        exn, CC, ew1, CC, exz, 2 * DIN, TOKS, 2 * DIN, CC, nullptr, nullptr);
    // 3. conv + SiLU
    conv_silu_kernel<<<(TOKS / 4) * DIN / 256, 256>>>(conv_w, conv_b);
    // 4. x_proj split-K GEMM  (PROFILED LAUNCH)
    gemm_mma<3, 128><<<dim3(1, TOKS / 128, SPLITK), 256, smem128>>>(
        exc, DIN, ew2, DIN, part, XDBL, TOKS, XDBL, DIN, nullptr, nullptr);
    // 5. reduce partials + dt_raw fp16
    reduce_part_kernel<<<(TOKS * XDBL + 255) / 256, 256>>>();
    // 6. dt_proj + softplus -> e_dt fp16
    gemm_mma<1, 128><<<dim3(DIN / 128, TOKS / 128), 256, smem128>>>(
        edtr, DTRANK, ew3, DTRANK, edt, DIN, TOKS, DIN, DTRANK, dt_proj_b, nullptr);
    // 7. selective scan + gate (v3: 4ch x 8st per warp)
    scan_kernel<<<(BB * DIN) / 32, 256>>>(A_log, Dvec);
    // 8. out_proj + residual, transposed store
    gemm_mma<2, 128><<<dim3(CC / 128, TOKS / 128), 256, smem128>>>(
        ey, DIN, ew4, DIN, out, 0, TOKS, CC, DIN, nullptr, x);
}